// round 15
// baseline (speedup 1.0000x reference)
#include <cuda_runtime.h>
#include <cuda_bf16.h>

#define Gn 512
#define An 24
#define Hd 128
#define NN (Gn*An)
#define NLAYER 4
#define EINW 325

// edge halves: W2 17408 | Wd(aug) 13056 | U 13056 | Fd 9984 ; floats S,C,Lat
#define EDGE_SMEM_BYTES ((17408+13056+13056+9984)*2 + (720+720+128)*4)
// latent: u32 sXc[48][68] | sWc[64][136] | sH[48][132] | sAt[48]
#define LAT_SMEM_BYTES ((48*68 + 64*136 + 48*132 + 48)*4)
// node_fused: sX [48][260] | chunk 8704 u32 | sY [48][132] | bias
#define NF_SMEM_BYTES ((48*260 + 8704 + 48*132)*4 + 1024)

// ---------------- scratch -----------------------------------------------------
__device__ float d_h[NN*Hd];
__device__ float d_P[NN*Hd];
__device__ float d_Q[NN*Hd];
__device__ float d_agg[NN*Hd];
__device__ float d_ts[NN*30];
__device__ float d_tc[NN*30];
__device__ float d_latips[Gn*9];
__device__ __align__(16) __nv_bfloat16 d_W2bf[NLAYER*128*136];
__device__ __align__(16) __nv_bfloat16 d_Wdbf[NLAYER*96*136];
__device__ __align__(16) unsigned d_W1t[NLAYER*256*136];   // tf32, padded
__device__ __align__(16) unsigned d_W2t[NLAYER*128*136];   // tf32, padded
__device__ __align__(16) unsigned d_Wabt[NLAYER*128*264];  // tf32 Wa|Wb, padded
__device__ __align__(16) unsigned d_Lwt[384*136];          // tf32 latent_w, padded

__device__ __forceinline__ float silu_f(float x){
    return __fdividef(x, 1.0f + __expf(-x));
}

__device__ __forceinline__ unsigned pack_bf2(float lo, float hi){
    unsigned r;
    asm("cvt.rn.bf16x2.f32 %0, %1, %2;" : "=r"(r) : "f"(hi), "f"(lo));
    return r;
}

__device__ __forceinline__ unsigned tf32_rna(float x){
    unsigned u;
    asm("cvt.rna.tf32.f32 %0, %1;" : "=r"(u) : "f"(x));
    return u;
}

__device__ __forceinline__ void ldsm4(unsigned& r0, unsigned& r1, unsigned& r2,
                                      unsigned& r3, const void* p){
    unsigned a = (unsigned)__cvta_generic_to_shared(p);
    asm volatile("ldmatrix.sync.aligned.m8n8.x4.shared.b16 {%0,%1,%2,%3}, [%4];"
        : "=r"(r0), "=r"(r1), "=r"(r2), "=r"(r3) : "r"(a));
}

__device__ __forceinline__ void ldsm4t(unsigned& r0, unsigned& r1, unsigned& r2,
                                       unsigned& r3, const void* p){
    unsigned a = (unsigned)__cvta_generic_to_shared(p);
    asm volatile("ldmatrix.sync.aligned.m8n8.x4.trans.shared.b16 {%0,%1,%2,%3}, [%4];"
        : "=r"(r0), "=r"(r1), "=r"(r2), "=r"(r3) : "r"(a));
}

__device__ __forceinline__ void mma16(float* d, const unsigned* a, const unsigned* b){
    asm volatile(
        "mma.sync.aligned.m16n8k16.row.col.f32.bf16.bf16.f32 "
        "{%0,%1,%2,%3}, {%4,%5,%6,%7}, {%8,%9}, {%0,%1,%2,%3};\n"
        : "+f"(d[0]), "+f"(d[1]), "+f"(d[2]), "+f"(d[3])
        : "r"(a[0]), "r"(a[1]), "r"(a[2]), "r"(a[3]), "r"(b[0]), "r"(b[1]));
}

__device__ __forceinline__ void mma8(float* d, const unsigned* a, const unsigned* b){
    asm volatile(
        "mma.sync.aligned.m16n8k8.row.col.f32.tf32.tf32.f32 "
        "{%0,%1,%2,%3}, {%4,%5,%6,%7}, {%8,%9}, {%0,%1,%2,%3};\n"
        : "+f"(d[0]), "+f"(d[1]), "+f"(d[2]), "+f"(d[3])
        : "r"(a[0]), "r"(a[1]), "r"(a[2]), "r"(a[3]), "r"(b[0]), "r"(b[1]));
}

// ---------------- weight pre-conversion (bf16 + tf32, padded) ------------------
__global__ void wconv_kernel(const float* __restrict__ ew1,
                             const float* __restrict__ ew2,
                             const float* __restrict__ nw1,
                             const float* __restrict__ nw2,
                             const float* __restrict__ lw){
    int idx = blockIdx.x*256 + threadIdx.x;
    if (idx < NLAYER*128*136){
        int l = idx/(128*136); int r = idx - l*128*136;
        int k = r/136, c = r - k*136;
        float v = (c<128) ? ew2[(l*128 + k)*Hd + c] : 0.f;
        d_W2bf[idx] = __float2bfloat16_rn(v);
        d_W2t[idx]  = tf32_rna((c<128) ? nw2[(l*128 + k)*Hd + c] : 0.f);
    }
    if (idx < NLAYER*96*136){
        int l = idx/(96*136); int r = idx - l*96*136;
        int k = r/136, c = r - k*136;
        float v = (k<60 && c<128) ? ew1[(l*EINW + 265 + k)*Hd + c] : 0.f;
        d_Wdbf[idx] = __float2bfloat16_rn(v);
    }
    if (idx < NLAYER*256*136){
        int l = idx/(256*136); int r = idx - l*256*136;
        int k = r/136, c = r - k*136;
        d_W1t[idx] = tf32_rna((c<128) ? nw1[(l*256 + k)*Hd + c] : 0.f);
    }
    if (idx < NLAYER*128*264){
        int l = idx/(128*264); int r = idx - l*128*264;
        int k = r/264, n = r - k*264;
        float v = 0.f;
        if (n < 128)      v = ew1[(l*EINW + k)*Hd + n];
        else if (n < 256) v = ew1[(l*EINW + 128 + k)*Hd + (n-128)];
        d_Wabt[idx] = tf32_rna(v);
    }
    if (idx < 384*136){
        int k = idx/136, c = idx - k*136;
        d_Lwt[idx] = tf32_rna((c<128) ? lw[k*Hd + c] : 0.f);
    }
}

// ---------------- per-node trig tables ----------------------------------------
__global__ void trig_kernel(const float* __restrict__ frac){
    int idx = blockIdx.x*blockDim.x + threadIdx.x;
    if (idx >= NN*30) return;
    int n = idx/30; int r = idx - n*30; int dd = r/10; int f = r - dd*10;
    float x = frac[n*3+dd];
    float th = 6.283185307179586f * (float)f * x;
    d_ts[idx] = sinf(th);
    d_tc[idx] = cosf(th);
}

// ---------------- latent (tf32 MMA) + fused layer-0 projection ----------------
__global__ void __launch_bounds__(256,2) latent_kernel(
    const float* __restrict__ t, const int* __restrict__ atom_types,
    const float* __restrict__ xrd, const float* __restrict__ emb,
    const float* __restrict__ lb)
{
    extern __shared__ __align__(16) unsigned lsm[];
    unsigned* sXc = lsm;                // [48][68]  per-chunk X (tf32)
    unsigned* sWc = lsm + 48*68;        // [64][136] weight chunk
    unsigned* sH  = lsm + 48*68 + 64*136;  // [48][132] h (tf32)
    int*      sAt = (int*)(sH + 48*132);   // [48] atom row indices
    unsigned* sWb = lsm;                // proj-phase alias ([32][264] = 8448 u32)

    int n0 = blockIdx.x*48;
    int gbase = n0/24;
    int tx = threadIdx.x;
    int warp = tx>>5, lane = tx&31;
    int gq = lane>>2, tg = lane&3;

    if (tx < 48) sAt[tx] = atom_types[n0+tx] - 1;
    __syncthreads();

    float acc[3][2][4];
    #pragma unroll
    for (int mt=0;mt<3;mt++)
        #pragma unroll
        for (int nt=0;nt<2;nt++)
            #pragma unroll
            for (int q=0;q<4;q++) acc[mt][nt][q] = 0.f;

    for (int kc=0; kc<6; kc++){
        {
            const uint4* src = (const uint4*)&d_Lwt[(kc*64)*136];
            uint4* dst = (uint4*)sWc;
            for (int i=tx; i<2176; i+=256) dst[i] = src[i];
        }
        for (int idx=tx; idx<48*16; idx+=256){
            int r = idx>>4; int q4 = idx&15; int kk = q4*4;
            int k = kc*64 + kk;
            int g = gbase + (r>=24 ? 1 : 0);
            float4 v;
            if (k < 128)      v = *(const float4*)&emb[sAt[r]*Hd + k];
            else if (k < 256) v = *(const float4*)&t[g*Hd + (k-128)];
            else              v = *(const float4*)&xrd[g*Hd + (k-256)];
            uint4 o;
            o.x = tf32_rna(v.x); o.y = tf32_rna(v.y);
            o.z = tf32_rna(v.z); o.w = tf32_rna(v.w);
            *(uint4*)&sXc[r*68 + kk] = o;
        }
        __syncthreads();
        #pragma unroll
        for (int kk=0;kk<8;kk++){
            int k0 = kk*8;
            unsigned ua[3][4], ub[2][2];
            #pragma unroll
            for (int mt=0;mt<3;mt++){
                int r = mt*16 + gq;
                ua[mt][0] = sXc[r*68 + k0+tg];
                ua[mt][1] = sXc[(r+8)*68 + k0+tg];
                ua[mt][2] = sXc[r*68 + k0+tg+4];
                ua[mt][3] = sXc[(r+8)*68 + k0+tg+4];
            }
            #pragma unroll
            for (int nt=0;nt<2;nt++){
                int c = warp*16 + nt*8 + gq;
                ub[nt][0] = sWc[(k0+tg)*136 + c];
                ub[nt][1] = sWc[(k0+tg+4)*136 + c];
            }
            #pragma unroll
            for (int mt=0;mt<3;mt++)
                #pragma unroll
                for (int nt=0;nt<2;nt++)
                    mma8(acc[mt][nt], ua[mt], ub[nt]);
        }
        __syncthreads();
    }

    #pragma unroll
    for (int mt=0;mt<3;mt++){
        #pragma unroll
        for (int nt=0;nt<2;nt++){
            int c = warp*16 + nt*8 + tg*2;
            float b0 = lb[c], b1 = lb[c+1];
            #pragma unroll
            for (int h=0;h<2;h++){
                int r = mt*16 + gq + h*8;
                float h0 = acc[mt][nt][2*h+0] + b0;
                float h1 = acc[mt][nt][2*h+1] + b1;
                *(float2*)&d_h[(n0+r)*Hd + c] = make_float2(h0, h1);
                sH[r*132 + c]   = tf32_rna(h0);
                sH[r*132 + c+1] = tf32_rna(h1);
            }
        }
    }

    float accp[3][4][4];
    #pragma unroll
    for (int mt=0;mt<3;mt++)
        #pragma unroll
        for (int nt=0;nt<4;nt++)
            #pragma unroll
            for (int q=0;q<4;q++) accp[mt][nt][q] = 0.f;

    for (int kc=0; kc<4; kc++){
        __syncthreads();
        {
            const uint4* src = (const uint4*)&d_Wabt[(kc*32)*264];
            uint4* dst = (uint4*)sWb;
            for (int i=tx; i<2112; i+=256) dst[i] = src[i];
        }
        __syncthreads();
        #pragma unroll
        for (int kk=0;kk<4;kk++){
            int ka = kc*32 + kk*8;
            int kb = kk*8;
            unsigned ua[3][4], ub[4][2];
            #pragma unroll
            for (int mt=0;mt<3;mt++){
                int r = mt*16 + gq;
                ua[mt][0] = sH[r*132 + ka+tg];
                ua[mt][1] = sH[(r+8)*132 + ka+tg];
                ua[mt][2] = sH[r*132 + ka+tg+4];
                ua[mt][3] = sH[(r+8)*132 + ka+tg+4];
            }
            #pragma unroll
            for (int nt=0;nt<4;nt++){
                int c = warp*32 + nt*8 + gq;
                ub[nt][0] = sWb[(kb+tg)*264 + c];
                ub[nt][1] = sWb[(kb+tg+4)*264 + c];
            }
            #pragma unroll
            for (int mt=0;mt<3;mt++)
                #pragma unroll
                for (int nt=0;nt<4;nt++)
                    mma8(accp[mt][nt], ua[mt], ub[nt]);
        }
    }
    #pragma unroll
    for (int mt=0;mt<3;mt++){
        #pragma unroll
        for (int nt=0;nt<4;nt++){
            int c = warp*32 + nt*8 + tg*2;
            #pragma unroll
            for (int h=0;h<2;h++){
                int r = mt*16 + gq + h*8;
                float2 v = make_float2(accp[mt][nt][2*h+0], accp[mt][nt][2*h+1]);
                if (c < 128) *(float2*)&d_P[(n0+r)*Hd + c] = v;
                else         *(float2*)&d_Q[(n0+r)*Hd + (c-128)] = v;
            }
        }
    }
}

// ---------------- lattice inner products --------------------------------------
__global__ void latips_kernel(const float* __restrict__ lat){
    int idx = blockIdx.x*blockDim.x + threadIdx.x;
    if (idx >= Gn*9) return;
    int g = idx/9; int rs = idx - g*9; int r = rs/3; int s = rs - r*3;
    const float* Lg = lat + g*9;
    d_latips[idx] = Lg[r*3]*Lg[s*3] + Lg[r*3+1]*Lg[s*3+1] + Lg[r*3+2]*Lg[s*3+2];
}

// ---------------- hot kernel: persistent bf16 edge MLP ------------------------
__global__ void __launch_bounds__(256,2) edge_kernel(
    const float* __restrict__ ew1, const float* __restrict__ eb1,
    const float* __restrict__ eb2, int l)
{
    extern __shared__ __align__(16) unsigned char smraw[];
    __nv_bfloat16* sW2h = (__nv_bfloat16*)smraw;     // [128][136]
    __nv_bfloat16* sWdh = sW2h + 17408;              // [96][136]
    __nv_bfloat16* sUh  = sWdh + 13056;              // [96][136]
    __nv_bfloat16* sFdh = sUh + 13056;               // [96][104]
    float* sS   = (float*)(sFdh + 9984);             // [24][30]
    float* sC   = sS  + 720;
    float* sLat = sC  + 720;                         // [128]

    int tx = threadIdx.x;
    int warp = tx>>5, lane = tx&31;
    int gq = lane>>2, tg = lane&3;
    int wx = warp&3, wy = warp>>2;
    int n0 = wx*32, m0 = wy*48;
    int row16 = lane & 15;
    int half8 = (lane & 16) ? 8 : 0;

    {
        const uint4* s2 = (const uint4*)&d_W2bf[l*128*136];
        uint4* t2 = (uint4*)sW2h;
        for (int i=tx; i<128*136/8; i+=256) t2[i] = s2[i];
        const uint4* sd = (const uint4*)&d_Wdbf[l*96*136];
        uint4* td = (uint4*)sWdh;
        for (int i=tx; i<64*136/8; i+=256) td[i] = sd[i];
        for (int i=tx; i<8*136/8;  i+=256) td[1496+i] = sd[1496+i];
    }
    float rb2[8];
    #pragma unroll
    for (int nt=0;nt<4;nt++)
        #pragma unroll
        for (int qq=0;qq<2;qq++)
            rb2[nt*2+qq] = eb2[l*Hd + n0 + nt*8 + tg*2 + qq];

    for (int gr = blockIdx.x; gr < Gn; gr += gridDim.x){
        for (int idx=tx; idx<24*32; idx+=256){
            int j = idx>>5, qq = idx&31;
            float4 v = *(const float4*)&d_Q[(gr*24+j)*Hd + qq*4];
            unsigned lo = pack_bf2(v.x, v.y);
            unsigned hi = pack_bf2(v.z, v.w);
            *(uint2*)&sWdh[(64+j)*136 + qq*4] = make_uint2(lo, hi);
        }
        for (int idx=tx; idx<720; idx+=256){
            sS[idx] = d_ts[gr*720 + idx];
            sC[idx] = d_tc[gr*720 + idx];
        }
        if (tx < 128){
            float acc = eb1[l*Hd + tx];
            const float* wc = ew1 + (l*EINW + 256)*Hd;
            #pragma unroll
            for (int k=0;k<9;k++) acc += d_latips[gr*9+k] * wc[k*Hd + tx];
            sLat[tx] = acc;
        }
        __syncthreads();

        for (int it=0; it<6; ++it){
            int i0 = it*4;
            for (int idx=tx; idx<96*30; idx+=256){
                int e = idx/30; int df = idx - e*30;
                int s = e/24; int j = e - s*24; int i = i0+s;
                float sj = sS[j*30+df], cj = sC[j*30+df];
                float si = sS[i*30+df], ci = sC[i*30+df];
                sFdh[e*104 + df]      = __float2bfloat16_rn(sj*ci - cj*si);
                sFdh[e*104 + 30 + df] = __float2bfloat16_rn(cj*ci + sj*si);
            }
            for (int idx=tx; idx<96*36; idx+=256){
                int e = idx/36; int k = 60 + (idx - e*36);
                int s = e/24; int j = e - s*24;
                float v = (k == 60+s || k == 64+j) ? 1.f : 0.f;
                sFdh[e*104 + k] = __float2bfloat16_rn(v);
            }
            for (int idx=tx; idx<4*Hd; idx+=256){
                int s = idx>>7, c = idx&127;
                sWdh[(60+s)*136 + c] =
                    __float2bfloat16_rn(d_P[(gr*24+i0+s)*Hd + c] + sLat[c]);
            }
            __syncthreads();

            float da[3][4][4];
            #pragma unroll
            for (int mt=0;mt<3;mt++)
                #pragma unroll
                for (int nt=0;nt<4;nt++)
                    #pragma unroll
                    for (int q=0;q<4;q++) da[mt][nt][q] = 0.f;
            #pragma unroll
            for (int kk=0;kk<6;kk++){
                int k0 = kk*16;
                unsigned ua[3][4], ub[4][2];
                #pragma unroll
                for (int mt=0;mt<3;mt++)
                    ldsm4(ua[mt][0],ua[mt][1],ua[mt][2],ua[mt][3],
                          &sFdh[(m0+mt*16+row16)*104 + k0 + half8]);
                #pragma unroll
                for (int np=0;np<2;np++){
                    unsigned t0,t1,t2,t3;
                    ldsm4t(t0,t1,t2,t3, &sWdh[(k0+row16)*136 + n0+np*16 + half8]);
                    ub[2*np][0]=t0; ub[2*np][1]=t1;
                    ub[2*np+1][0]=t2; ub[2*np+1][1]=t3;
                }
                #pragma unroll
                for (int mt=0;mt<3;mt++)
                    #pragma unroll
                    for (int nt=0;nt<4;nt++)
                        mma16(da[mt][nt], ua[mt], ub[nt]);
            }

            #pragma unroll
            for (int mt=0;mt<3;mt++){
                #pragma unroll
                for (int nt=0;nt<4;nt++){
                    int c = n0 + nt*8 + tg*2;
                    #pragma unroll
                    for (int h=0; h<2; h++){
                        int r = m0 + mt*16 + gq + h*8;
                        float v0 = silu_f(da[mt][nt][2*h+0]);
                        float v1 = silu_f(da[mt][nt][2*h+1]);
                        *(unsigned*)&sUh[r*136 + c] = pack_bf2(v0, v1);
                    }
                }
            }
            __syncthreads();

            float de[3][4][4];
            #pragma unroll
            for (int mt=0;mt<3;mt++)
                #pragma unroll
                for (int nt=0;nt<4;nt++)
                    #pragma unroll
                    for (int q=0;q<4;q++) de[mt][nt][q] = 0.f;
            #pragma unroll
            for (int kk=0;kk<8;kk++){
                int k0 = kk*16;
                unsigned ua[3][4], ub[4][2];
                #pragma unroll
                for (int mt=0;mt<3;mt++)
                    ldsm4(ua[mt][0],ua[mt][1],ua[mt][2],ua[mt][3],
                          &sUh[(m0+mt*16+row16)*136 + k0 + half8]);
                #pragma unroll
                for (int np=0;np<2;np++){
                    unsigned t0,t1,t2,t3;
                    ldsm4t(t0,t1,t2,t3, &sW2h[(k0+row16)*136 + n0+np*16 + half8]);
                    ub[2*np][0]=t0; ub[2*np][1]=t1;
                    ub[2*np+1][0]=t2; ub[2*np+1][1]=t3;
                }
                #pragma unroll
                for (int mt=0;mt<3;mt++)
                    #pragma unroll
                    for (int nt=0;nt<4;nt++)
                        mma16(de[mt][nt], ua[mt], ub[nt]);
            }
            int iA = i0 + wy*2, iB = iA + 1;
            #pragma unroll
            for (int nt=0;nt<4;nt++){
                #pragma unroll
                for (int qq=0;qq<2;qq++){
                    int c = n0 + nt*8 + tg*2 + qq;
                    float b = rb2[nt*2+qq];
                    float s0 = silu_f(de[0][nt][qq]+b) + silu_f(de[0][nt][2+qq]+b)
                             + silu_f(de[1][nt][qq]+b);
                    float s1 = silu_f(de[1][nt][2+qq]+b) + silu_f(de[2][nt][qq]+b)
                             + silu_f(de[2][nt][2+qq]+b);
                    #pragma unroll
                    for (int off=4;off<32;off<<=1){
                        s0 += __shfl_xor_sync(0xffffffffu, s0, off);
                        s1 += __shfl_xor_sync(0xffffffffu, s1, off);
                    }
                    if (gq == 0){
                        d_agg[(gr*24 + iA)*Hd + c] = s0 * (1.0f/24.0f);
                        d_agg[(gr*24 + iB)*Hd + c] = s1 * (1.0f/24.0f);
                    }
                }
            }
            __syncthreads();
        }
    }
}

// ---------------- fused node MLP + next proj (tf32, 2 graphs/CTA, 2 CTA/SM) ---
__global__ void __launch_bounds__(256,2) node_fused(
    const float* __restrict__ nb1, const float* __restrict__ nb2,
    int l, int do_proj)
{
    extern __shared__ __align__(16) unsigned smu[];
    unsigned* sX  = smu;               // [48][260]
    unsigned* sWb = sX + 48*260;       // chunk buffer (8704 u32)
    unsigned* sY  = sWb + 8704;        // [48][132]
    float* sB = (float*)(sY + 48*132); // b1[128] | b2[128]
    unsigned* sH = sY;                 // proj-phase alias

    int r0g = blockIdx.x*48;
    int tx = threadIdx.x;
    int warp = tx>>5, lane = tx&31;
    int gq = lane>>2, tg = lane&3;

    for (int idx=tx; idx<48*64; idx+=256){
        int r = idx>>6; int q = idx&63;
        float4 v = (q<32) ? *(const float4*)&d_h[(r0g+r)*Hd + q*4]
                          : *(const float4*)&d_agg[(r0g+r)*Hd + (q-32)*4];
        uint4 o;
        o.x = tf32_rna(v.x); o.y = tf32_rna(v.y);
        o.z = tf32_rna(v.z); o.w = tf32_rna(v.w);
        *(uint4*)&sX[r*260 + q*4] = o;
    }
    if (tx < 128){ sB[tx] = nb1[l*Hd+tx]; sB[128+tx] = nb2[l*Hd+tx]; }

    float a1[3][2][4];
    #pragma unroll
    for (int mt=0;mt<3;mt++)
        #pragma unroll
        for (int nt=0;nt<2;nt++)
            #pragma unroll
            for (int q=0;q<4;q++) a1[mt][nt][q] = 0.f;

    for (int kc=0; kc<4; kc++){
        {
            const uint4* src = (const uint4*)&d_W1t[(l*256 + kc*64)*136];
            uint4* dst = (uint4*)sWb;
            for (int i=tx; i<2176; i+=256) dst[i] = src[i];
        }
        __syncthreads();
        #pragma unroll
        for (int kk=0;kk<8;kk++){
            int ka = kc*64 + kk*8;
            int kb = kk*8;
            unsigned ua[3][4], ub[2][2];
            #pragma unroll
            for (int mt=0;mt<3;mt++){
                int r = mt*16 + gq;
                ua[mt][0] = sX[r*260 + ka+tg];
                ua[mt][1] = sX[(r+8)*260 + ka+tg];
                ua[mt][2] = sX[r*260 + ka+tg+4];
                ua[mt][3] = sX[(r+8)*260 + ka+tg+4];
            }
            #pragma unroll
            for (int nt=0;nt<2;nt++){
                int c = warp*16 + nt*8 + gq;
                ub[nt][0] = sWb[(kb+tg)*136 + c];
                ub[nt][1] = sWb[(kb+tg+4)*136 + c];
            }
            #pragma unroll
            for (int mt=0;mt<3;mt++)
                #pragma unroll
                for (int nt=0;nt<2;nt++)
                    mma8(a1[mt][nt], ua[mt], ub[nt]);
        }
        __syncthreads();
    }

    #pragma unroll
    for (int mt=0;mt<3;mt++){
        #pragma unroll
        for (int nt=0;nt<2;nt++){
            int c = warp*16 + nt*8 + tg*2;
            #pragma unroll
            for (int h=0;h<2;h++){
                int r = mt*16 + gq + h*8;
                sY[r*132 + c]   = tf32_rna(silu_f(a1[mt][nt][2*h+0] + sB[c]));
                sY[r*132 + c+1] = tf32_rna(silu_f(a1[mt][nt][2*h+1] + sB[c+1]));
            }
        }
    }

    float a2[3][2][4];
    #pragma unroll
    for (int mt=0;mt<3;mt++)
        #pragma unroll
        for (int nt=0;nt<2;nt++)
            #pragma unroll
            for (int q=0;q<4;q++) a2[mt][nt][q] = 0.f;

    for (int kc=0; kc<2; kc++){
        __syncthreads();
        {
            const uint4* src = (const uint4*)&d_W2t[(l*128 + kc*64)*136];
            uint4* dst = (uint4*)sWb;
            for (int i=tx; i<2176; i+=256) dst[i] = src[i];
        }
        __syncthreads();
        #pragma unroll
        for (int kk=0;kk<8;kk++){
            int ka = kc*64 + kk*8;
            int kb = kk*8;
            unsigned ua[3][4], ub[2][2];
            #pragma unroll
            for (int mt=0;mt<3;mt++){
                int r = mt*16 + gq;
                ua[mt][0] = sY[r*132 + ka+tg];
                ua[mt][1] = sY[(r+8)*132 + ka+tg];
                ua[mt][2] = sY[r*132 + ka+tg+4];
                ua[mt][3] = sY[(r+8)*132 + ka+tg+4];
            }
            #pragma unroll
            for (int nt=0;nt<2;nt++){
                int c = warp*16 + nt*8 + gq;
                ub[nt][0] = sWb[(kb+tg)*136 + c];
                ub[nt][1] = sWb[(kb+tg+4)*136 + c];
            }
            #pragma unroll
            for (int mt=0;mt<3;mt++)
                #pragma unroll
                for (int nt=0;nt<2;nt++)
                    mma8(a2[mt][nt], ua[mt], ub[nt]);
        }
    }
    __syncthreads();

    float nh[3][2][4];
    #pragma unroll
    for (int mt=0;mt<3;mt++){
        #pragma unroll
        for (int nt=0;nt<2;nt++){
            int c = warp*16 + nt*8 + tg*2;
            #pragma unroll
            for (int h=0;h<2;h++){
                int r = mt*16 + gq + h*8;
                float o0 = silu_f(a2[mt][nt][2*h+0] + sB[128+c]);
                float o1 = silu_f(a2[mt][nt][2*h+1] + sB[128+c+1]);
                float2* p = (float2*)&d_h[(r0g+r)*Hd + c];
                float2 old = *p;
                old.x += o0; old.y += o1;
                *p = old;
                nh[mt][nt][2*h+0] = old.x;
                nh[mt][nt][2*h+1] = old.y;
            }
        }
    }
    if (!do_proj) return;

    #pragma unroll
    for (int mt=0;mt<3;mt++){
        #pragma unroll
        for (int nt=0;nt<2;nt++){
            int c = warp*16 + nt*8 + tg*2;
            #pragma unroll
            for (int h=0;h<2;h++){
                int r = mt*16 + gq + h*8;
                sH[r*132 + c]   = tf32_rna(nh[mt][nt][2*h+0]);
                sH[r*132 + c+1] = tf32_rna(nh[mt][nt][2*h+1]);
            }
        }
    }
    int lp = l+1;
    float accp[3][4][4];
    #pragma unroll
    for (int mt=0;mt<3;mt++)
        #pragma unroll
        for (int nt=0;nt<4;nt++)
            #pragma unroll
            for (int q=0;q<4;q++) accp[mt][nt][q] = 0.f;

    for (int kc=0; kc<4; kc++){
        __syncthreads();
        {
            const uint4* src = (const uint4*)&d_Wabt[(lp*128 + kc*32)*264];
            uint4* dst = (uint4*)sWb;
            for (int i=tx; i<2112; i+=256) dst[i] = src[i];
        }
        __syncthreads();
        #pragma unroll
        for (int kk=0;kk<4;kk++){
            int ka = kc*32 + kk*8;
            int kb = kk*8;
            unsigned ua[3][4], ub[4][2];
            #pragma unroll
            for (int mt=0;mt<3;mt++){
                int r = mt*16 + gq;
                ua[mt][0] = sH[r*132 + ka+tg];
                ua[mt][1] = sH[(r+8)*132 + ka+tg];
                ua[mt][2] = sH[r*132 + ka+tg+4];
                ua[mt][3] = sH[(r+8)*132 + ka+tg+4];
            }
            #pragma unroll
            for (int nt=0;nt<4;nt++){
                int c = warp*32 + nt*8 + gq;
                ub[nt][0] = sWb[(kb+tg)*264 + c];
                ub[nt][1] = sWb[(kb+tg+4)*264 + c];
            }
            #pragma unroll
            for (int mt=0;mt<3;mt++)
                #pragma unroll
                for (int nt=0;nt<4;nt++)
                    mma8(accp[mt][nt], ua[mt], ub[nt]);
        }
    }
    #pragma unroll
    for (int mt=0;mt<3;mt++){
        #pragma unroll
        for (int nt=0;nt<4;nt++){
            int c = warp*32 + nt*8 + tg*2;
            #pragma unroll
            for (int h=0;h<2;h++){
                int r = mt*16 + gq + h*8;
                float2 v = make_float2(accp[mt][nt][2*h+0], accp[mt][nt][2*h+1]);
                if (c < 128) *(float2*)&d_P[(r0g+r)*Hd + c] = v;
                else         *(float2*)&d_Q[(r0g+r)*Hd + (c-128)] = v;
            }
        }
    }
}

// ---------------- final heads -------------------------------------------------
__global__ void __launch_bounds__(128) final_kernel(
    const float* __restrict__ lat, const float* __restrict__ cw,
    const float* __restrict__ lw, float* __restrict__ out)
{
    __shared__ float sh[24*Hd];
    __shared__ float sgf[Hd];
    __shared__ float smid[9];
    __shared__ float scw[Hd*3];
    int g = blockIdx.x; int tx = threadIdx.x;
    for (int idx=tx; idx<24*Hd; idx+=128) sh[idx] = d_h[g*24*Hd + idx];
    for (int idx=tx; idx<Hd*3; idx+=128) scw[idx] = cw[idx];
    __syncthreads();
    {
        float acc = 0.f;
        #pragma unroll
        for (int a=0;a<24;a++) acc += sh[a*Hd + tx];
        sgf[tx] = acc * (1.0f/24.0f);
    }
    if (tx < 72){
        int n = tx/3; int dd = tx - n*3;
        float s = 0.f;
        #pragma unroll 4
        for (int k=0;k<Hd;k++) s += sh[n*Hd+k]*scw[k*3+dd];
        out[Gn*9 + (g*24+n)*3 + dd] = s;
    }
    __syncthreads();
    if (tx < 9){
        float s = 0.f;
        #pragma unroll 4
        for (int k=0;k<Hd;k++) s += sgf[k]*lw[k*9+tx];
        smid[tx] = s;
    }
    __syncthreads();
    if (tx < 9){
        int r = tx/3; int sc = tx - r*3;
        const float* Lg = lat + g*9;
        out[g*9+tx] = smid[r*3+0]*Lg[0+sc] + smid[r*3+1]*Lg[3+sc]
                    + smid[r*3+2]*Lg[6+sc];
    }
}

// ---------------- launch ------------------------------------------------------
extern "C" void kernel_launch(void* const* d_in, const int* in_sizes, int n_in,
                              void* d_out, int out_size)
{
    const float* t          = (const float*)d_in[0];
    const int*   atom_types = (const int*)  d_in[1];
    const float* frac       = (const float*)d_in[2];
    const float* lattices   = (const float*)d_in[3];
    const float* xrd        = (const float*)d_in[6];
    const float* emb        = (const float*)d_in[7];
    const float* latent_w   = (const float*)d_in[8];
    const float* latent_b   = (const float*)d_in[9];
    const float* edge_w1    = (const float*)d_in[10];
    const float* edge_b1    = (const float*)d_in[11];
    const float* edge_w2    = (const float*)d_in[12];
    const float* edge_b2    = (const float*)d_in[13];
    const float* node_w1    = (const float*)d_in[14];
    const float* node_b1    = (const float*)d_in[15];
    const float* node_w2    = (const float*)d_in[16];
    const float* node_b2    = (const float*)d_in[17];
    const float* coord_w    = (const float*)d_in[18];
    const float* lattice_w  = (const float*)d_in[19];
    float* out = (float*)d_out;

    cudaFuncSetAttribute(edge_kernel,
        cudaFuncAttributeMaxDynamicSharedMemorySize, EDGE_SMEM_BYTES);
    cudaFuncSetAttribute(latent_kernel,
        cudaFuncAttributeMaxDynamicSharedMemorySize, LAT_SMEM_BYTES);
    cudaFuncSetAttribute(node_fused,
        cudaFuncAttributeMaxDynamicSharedMemorySize, NF_SMEM_BYTES);

    trig_kernel<<<(NN*30 + 255)/256, 256>>>(frac);
    latips_kernel<<<(Gn*9 + 255)/256, 256>>>(lattices);
    wconv_kernel<<<(NLAYER*256*136 + 255)/256, 256>>>(edge_w1, edge_w2,
                                                      node_w1, node_w2, latent_w);
    latent_kernel<<<NN/48, 256, LAT_SMEM_BYTES>>>(t, atom_types, xrd, emb, latent_b);

    for (int l=0; l<NLAYER; ++l){
        edge_kernel<<<Gn/2, 256, EDGE_SMEM_BYTES>>>(edge_w1, edge_b1, edge_b2, l);
        node_fused<<<Gn/2, 256, NF_SMEM_BYTES>>>(node_b1, node_b2, l, l < NLAYER-1);
    }

    final_kernel<<<Gn, 128>>>(lattices, coord_w, lattice_w, out);
}

// round 16
// speedup vs baseline: 1.0509x; 1.0509x over previous
#include <cuda_runtime.h>
#include <cuda_bf16.h>

#define Gn 512
#define An 24
#define Hd 128
#define NN (Gn*An)
#define NLAYER 4
#define EINW 325

// edge halves: W2 17408 | Wd(aug) 13056 | U 13056 | Fd 9984 ; floats S,C,Lat
#define EDGE_SMEM_BYTES ((17408+13056+13056+9984)*2 + (720+720+128)*4)
// latent: u32 sXc[48][68] | sWc[64][136] | sH[48][132] | sAt[48]
#define LAT_SMEM_BYTES ((48*68 + 64*136 + 48*132 + 48)*4)
// node_fused: sX [48][260] | chunk 8704 u32 | sY [48][132] | bias
#define NF_SMEM_BYTES ((48*260 + 8704 + 48*132)*4 + 1024)

// ---------------- scratch -----------------------------------------------------
__device__ float d_h[NN*Hd];
__device__ float d_P[NN*Hd];
__device__ float d_Q[NN*Hd];
__device__ float d_agg[NN*Hd];
__device__ float d_ts[NN*30];
__device__ float d_tc[NN*30];
__device__ float d_latips[Gn*9];
__device__ __align__(16) __nv_bfloat16 d_W2bf[NLAYER*128*136];
__device__ __align__(16) __nv_bfloat16 d_Wdbf[NLAYER*96*136];
__device__ __align__(16) unsigned d_W1t[NLAYER*256*136];   // tf32, padded
__device__ __align__(16) unsigned d_W2t[NLAYER*128*136];   // tf32, padded
__device__ __align__(16) unsigned d_Wabt[NLAYER*128*264];  // tf32 Wa|Wb, padded
__device__ __align__(16) unsigned d_Lwt[384*136];          // tf32 latent_w, padded

__device__ __forceinline__ float silu_f(float x){
    return __fdividef(x, 1.0f + __expf(-x));
}

__device__ __forceinline__ unsigned pack_bf2(float lo, float hi){
    unsigned r;
    asm("cvt.rn.bf16x2.f32 %0, %1, %2;" : "=r"(r) : "f"(hi), "f"(lo));
    return r;
}

__device__ __forceinline__ unsigned tf32_rna(float x){
    unsigned u;
    asm("cvt.rna.tf32.f32 %0, %1;" : "=r"(u) : "f"(x));
    return u;
}

__device__ __forceinline__ void ldsm4(unsigned& r0, unsigned& r1, unsigned& r2,
                                      unsigned& r3, const void* p){
    unsigned a = (unsigned)__cvta_generic_to_shared(p);
    asm volatile("ldmatrix.sync.aligned.m8n8.x4.shared.b16 {%0,%1,%2,%3}, [%4];"
        : "=r"(r0), "=r"(r1), "=r"(r2), "=r"(r3) : "r"(a));
}

__device__ __forceinline__ void ldsm4t(unsigned& r0, unsigned& r1, unsigned& r2,
                                       unsigned& r3, const void* p){
    unsigned a = (unsigned)__cvta_generic_to_shared(p);
    asm volatile("ldmatrix.sync.aligned.m8n8.x4.trans.shared.b16 {%0,%1,%2,%3}, [%4];"
        : "=r"(r0), "=r"(r1), "=r"(r2), "=r"(r3) : "r"(a));
}

__device__ __forceinline__ void mma16(float* d, const unsigned* a, const unsigned* b){
    asm volatile(
        "mma.sync.aligned.m16n8k16.row.col.f32.bf16.bf16.f32 "
        "{%0,%1,%2,%3}, {%4,%5,%6,%7}, {%8,%9}, {%0,%1,%2,%3};\n"
        : "+f"(d[0]), "+f"(d[1]), "+f"(d[2]), "+f"(d[3])
        : "r"(a[0]), "r"(a[1]), "r"(a[2]), "r"(a[3]), "r"(b[0]), "r"(b[1]));
}

__device__ __forceinline__ void mma8(float* d, const unsigned* a, const unsigned* b){
    asm volatile(
        "mma.sync.aligned.m16n8k8.row.col.f32.tf32.tf32.f32 "
        "{%0,%1,%2,%3}, {%4,%5,%6,%7}, {%8,%9}, {%0,%1,%2,%3};\n"
        : "+f"(d[0]), "+f"(d[1]), "+f"(d[2]), "+f"(d[3])
        : "r"(a[0]), "r"(a[1]), "r"(a[2]), "r"(a[3]), "r"(b[0]), "r"(b[1]));
}

// ---------------- weight pre-conversion (bf16 + tf32, padded) ------------------
__global__ void wconv_kernel(const float* __restrict__ ew1,
                             const float* __restrict__ ew2,
                             const float* __restrict__ nw1,
                             const float* __restrict__ nw2,
                             const float* __restrict__ lw){
    int idx = blockIdx.x*256 + threadIdx.x;
    if (idx < NLAYER*128*136){
        int l = idx/(128*136); int r = idx - l*128*136;
        int k = r/136, c = r - k*136;
        float v = (c<128) ? ew2[(l*128 + k)*Hd + c] : 0.f;
        d_W2bf[idx] = __float2bfloat16_rn(v);
        d_W2t[idx]  = tf32_rna((c<128) ? nw2[(l*128 + k)*Hd + c] : 0.f);
    }
    if (idx < NLAYER*96*136){
        int l = idx/(96*136); int r = idx - l*96*136;
        int k = r/136, c = r - k*136;
        float v = (k<60 && c<128) ? ew1[(l*EINW + 265 + k)*Hd + c] : 0.f;
        d_Wdbf[idx] = __float2bfloat16_rn(v);
    }
    if (idx < NLAYER*256*136){
        int l = idx/(256*136); int r = idx - l*256*136;
        int k = r/136, c = r - k*136;
        d_W1t[idx] = tf32_rna((c<128) ? nw1[(l*256 + k)*Hd + c] : 0.f);
    }
    if (idx < NLAYER*128*264){
        int l = idx/(128*264); int r = idx - l*128*264;
        int k = r/264, n = r - k*264;
        float v = 0.f;
        if (n < 128)      v = ew1[(l*EINW + k)*Hd + n];
        else if (n < 256) v = ew1[(l*EINW + 128 + k)*Hd + (n-128)];
        d_Wabt[idx] = tf32_rna(v);
    }
    if (idx < 384*136){
        int k = idx/136, c = idx - k*136;
        d_Lwt[idx] = tf32_rna((c<128) ? lw[k*Hd + c] : 0.f);
    }
}

// ---------------- per-node trig tables ----------------------------------------
__global__ void trig_kernel(const float* __restrict__ frac){
    int idx = blockIdx.x*blockDim.x + threadIdx.x;
    if (idx >= NN*30) return;
    int n = idx/30; int r = idx - n*30; int dd = r/10; int f = r - dd*10;
    float x = frac[n*3+dd];
    float th = 6.283185307179586f * (float)f * x;
    d_ts[idx] = sinf(th);
    d_tc[idx] = cosf(th);
}

// ---------------- latent (tf32 MMA) + fused layer-0 projection ----------------
__global__ void __launch_bounds__(256,2) latent_kernel(
    const float* __restrict__ t, const int* __restrict__ atom_types,
    const float* __restrict__ xrd, const float* __restrict__ emb,
    const float* __restrict__ lb)
{
    extern __shared__ __align__(16) unsigned lsm[];
    unsigned* sXc = lsm;                // [48][68]
    unsigned* sWc = lsm + 48*68;        // [64][136]
    unsigned* sH  = lsm + 48*68 + 64*136;  // [48][132]
    int*      sAt = (int*)(sH + 48*132);   // [48]
    unsigned* sWb = lsm;                // proj-phase alias

    int n0 = blockIdx.x*48;
    int gbase = n0/24;
    int tx = threadIdx.x;
    int warp = tx>>5, lane = tx&31;
    int gq = lane>>2, tg = lane&3;

    if (tx < 48) sAt[tx] = atom_types[n0+tx] - 1;
    __syncthreads();

    float acc[3][2][4];
    #pragma unroll
    for (int mt=0;mt<3;mt++)
        #pragma unroll
        for (int nt=0;nt<2;nt++)
            #pragma unroll
            for (int q=0;q<4;q++) acc[mt][nt][q] = 0.f;

    for (int kc=0; kc<6; kc++){
        {
            const uint4* src = (const uint4*)&d_Lwt[(kc*64)*136];
            uint4* dst = (uint4*)sWc;
            for (int i=tx; i<2176; i+=256) dst[i] = src[i];
        }
        for (int idx=tx; idx<48*16; idx+=256){
            int r = idx>>4; int q4 = idx&15; int kk = q4*4;
            int k = kc*64 + kk;
            int g = gbase + (r>=24 ? 1 : 0);
            float4 v;
            if (k < 128)      v = *(const float4*)&emb[sAt[r]*Hd + k];
            else if (k < 256) v = *(const float4*)&t[g*Hd + (k-128)];
            else              v = *(const float4*)&xrd[g*Hd + (k-256)];
            uint4 o;
            o.x = tf32_rna(v.x); o.y = tf32_rna(v.y);
            o.z = tf32_rna(v.z); o.w = tf32_rna(v.w);
            *(uint4*)&sXc[r*68 + kk] = o;
        }
        __syncthreads();
        #pragma unroll
        for (int kk=0;kk<8;kk++){
            int k0 = kk*8;
            unsigned ua[3][4], ub[2][2];
            #pragma unroll
            for (int mt=0;mt<3;mt++){
                int r = mt*16 + gq;
                ua[mt][0] = sXc[r*68 + k0+tg];
                ua[mt][1] = sXc[(r+8)*68 + k0+tg];
                ua[mt][2] = sXc[r*68 + k0+tg+4];
                ua[mt][3] = sXc[(r+8)*68 + k0+tg+4];
            }
            #pragma unroll
            for (int nt=0;nt<2;nt++){
                int c = warp*16 + nt*8 + gq;
                ub[nt][0] = sWc[(k0+tg)*136 + c];
                ub[nt][1] = sWc[(k0+tg+4)*136 + c];
            }
            #pragma unroll
            for (int mt=0;mt<3;mt++)
                #pragma unroll
                for (int nt=0;nt<2;nt++)
                    mma8(acc[mt][nt], ua[mt], ub[nt]);
        }
        __syncthreads();
    }

    #pragma unroll
    for (int mt=0;mt<3;mt++){
        #pragma unroll
        for (int nt=0;nt<2;nt++){
            int c = warp*16 + nt*8 + tg*2;
            float b0 = lb[c], b1 = lb[c+1];
            #pragma unroll
            for (int h=0;h<2;h++){
                int r = mt*16 + gq + h*8;
                float h0 = acc[mt][nt][2*h+0] + b0;
                float h1 = acc[mt][nt][2*h+1] + b1;
                *(float2*)&d_h[(n0+r)*Hd + c] = make_float2(h0, h1);
                sH[r*132 + c]   = tf32_rna(h0);
                sH[r*132 + c+1] = tf32_rna(h1);
            }
        }
    }

    float accp[3][4][4];
    #pragma unroll
    for (int mt=0;mt<3;mt++)
        #pragma unroll
        for (int nt=0;nt<4;nt++)
            #pragma unroll
            for (int q=0;q<4;q++) accp[mt][nt][q] = 0.f;

    for (int kc=0; kc<4; kc++){
        __syncthreads();
        {
            const uint4* src = (const uint4*)&d_Wabt[(kc*32)*264];
            uint4* dst = (uint4*)sWb;
            for (int i=tx; i<2112; i+=256) dst[i] = src[i];
        }
        __syncthreads();
        #pragma unroll
        for (int kk=0;kk<4;kk++){
            int ka = kc*32 + kk*8;
            int kb = kk*8;
            unsigned ua[3][4], ub[4][2];
            #pragma unroll
            for (int mt=0;mt<3;mt++){
                int r = mt*16 + gq;
                ua[mt][0] = sH[r*132 + ka+tg];
                ua[mt][1] = sH[(r+8)*132 + ka+tg];
                ua[mt][2] = sH[r*132 + ka+tg+4];
                ua[mt][3] = sH[(r+8)*132 + ka+tg+4];
            }
            #pragma unroll
            for (int nt=0;nt<4;nt++){
                int c = warp*32 + nt*8 + gq;
                ub[nt][0] = sWb[(kb+tg)*264 + c];
                ub[nt][1] = sWb[(kb+tg+4)*264 + c];
            }
            #pragma unroll
            for (int mt=0;mt<3;mt++)
                #pragma unroll
                for (int nt=0;nt<4;nt++)
                    mma8(accp[mt][nt], ua[mt], ub[nt]);
        }
    }
    #pragma unroll
    for (int mt=0;mt<3;mt++){
        #pragma unroll
        for (int nt=0;nt<4;nt++){
            int c = warp*32 + nt*8 + tg*2;
            #pragma unroll
            for (int h=0;h<2;h++){
                int r = mt*16 + gq + h*8;
                float2 v = make_float2(accp[mt][nt][2*h+0], accp[mt][nt][2*h+1]);
                if (c < 128) *(float2*)&d_P[(n0+r)*Hd + c] = v;
                else         *(float2*)&d_Q[(n0+r)*Hd + (c-128)] = v;
            }
        }
    }
}

// ---------------- lattice inner products --------------------------------------
__global__ void latips_kernel(const float* __restrict__ lat){
    int idx = blockIdx.x*blockDim.x + threadIdx.x;
    if (idx >= Gn*9) return;
    int g = idx/9; int rs = idx - g*9; int r = rs/3; int s = rs - r*3;
    const float* Lg = lat + g*9;
    d_latips[idx] = Lg[r*3]*Lg[s*3] + Lg[r*3+1]*Lg[s*3+1] + Lg[r*3+2]*Lg[s*3+2];
}

// ---------------- hot kernel: persistent bf16 edge MLP ------------------------
__global__ void __launch_bounds__(256,2) edge_kernel(
    const float* __restrict__ ew1, const float* __restrict__ eb1,
    const float* __restrict__ eb2, int l)
{
    extern __shared__ __align__(16) unsigned char smraw[];
    __nv_bfloat16* sW2h = (__nv_bfloat16*)smraw;     // [128][136]
    __nv_bfloat16* sWdh = sW2h + 17408;              // [96][136]
    __nv_bfloat16* sUh  = sWdh + 13056;              // [96][136]
    __nv_bfloat16* sFdh = sUh + 13056;               // [96][104]
    float* sS   = (float*)(sFdh + 9984);             // [24][30]
    float* sC   = sS  + 720;
    float* sLat = sC  + 720;                         // [128]

    int tx = threadIdx.x;
    int warp = tx>>5, lane = tx&31;
    int gq = lane>>2, tg = lane&3;
    int wx = warp&3, wy = warp>>2;
    int n0 = wx*32, m0 = wy*48;
    int row16 = lane & 15;
    int half8 = (lane & 16) ? 8 : 0;

    {
        const uint4* s2 = (const uint4*)&d_W2bf[l*128*136];
        uint4* t2 = (uint4*)sW2h;
        for (int i=tx; i<128*136/8; i+=256) t2[i] = s2[i];
        const uint4* sd = (const uint4*)&d_Wdbf[l*96*136];
        uint4* td = (uint4*)sWdh;
        for (int i=tx; i<64*136/8; i+=256) td[i] = sd[i];
        for (int i=tx; i<8*136/8;  i+=256) td[1496+i] = sd[1496+i];
    }
    // one-hot Fd block (cols 60-95): invariant across tiles AND graphs — write once
    for (int idx=tx; idx<96*36; idx+=256){
        int e = idx/36; int k = 60 + (idx - e*36);
        int s = e/24; int j = e - s*24;
        float v = (k == 60+s || k == 64+j) ? 1.f : 0.f;
        sFdh[e*104 + k] = __float2bfloat16_rn(v);
    }
    float rb2[8];
    #pragma unroll
    for (int nt=0;nt<4;nt++)
        #pragma unroll
        for (int qq=0;qq<2;qq++)
            rb2[nt*2+qq] = eb2[l*Hd + n0 + nt*8 + tg*2 + qq];

    for (int gr = blockIdx.x; gr < Gn; gr += gridDim.x){
        for (int idx=tx; idx<24*32; idx+=256){
            int j = idx>>5, qq = idx&31;
            float4 v = *(const float4*)&d_Q[(gr*24+j)*Hd + qq*4];
            unsigned lo = pack_bf2(v.x, v.y);
            unsigned hi = pack_bf2(v.z, v.w);
            *(uint2*)&sWdh[(64+j)*136 + qq*4] = make_uint2(lo, hi);
        }
        for (int idx=tx; idx<720; idx+=256){
            sS[idx] = d_ts[gr*720 + idx];
            sC[idx] = d_tc[gr*720 + idx];
        }
        if (tx < 128){
            float acc = eb1[l*Hd + tx];
            const float* wc = ew1 + (l*EINW + 256)*Hd;
            #pragma unroll
            for (int k=0;k<9;k++) acc += d_latips[gr*9+k] * wc[k*Hd + tx];
            sLat[tx] = acc;
        }
        __syncthreads();

        for (int it=0; it<6; ++it){
            int i0 = it*4;
            // trig pairs (cols 0-59 only; one-hot block persists)
            for (int idx=tx; idx<96*30; idx+=256){
                int e = idx/30; int df = idx - e*30;
                int s = e/24; int j = e - s*24; int i = i0+s;
                float sj = sS[j*30+df], cj = sC[j*30+df];
                float si = sS[i*30+df], ci = sC[i*30+df];
                sFdh[e*104 + df]      = __float2bfloat16_rn(sj*ci - cj*si);
                sFdh[e*104 + 30 + df] = __float2bfloat16_rn(cj*ci + sj*si);
            }
            for (int idx=tx; idx<4*Hd; idx+=256){
                int s = idx>>7, c = idx&127;
                sWdh[(60+s)*136 + c] =
                    __float2bfloat16_rn(d_P[(gr*24+i0+s)*Hd + c] + sLat[c]);
            }
            __syncthreads();   // sync(1): build -> GEMM-A

            float da[3][4][4];
            #pragma unroll
            for (int mt=0;mt<3;mt++)
                #pragma unroll
                for (int nt=0;nt<4;nt++)
                    #pragma unroll
                    for (int q=0;q<4;q++) da[mt][nt][q] = 0.f;
            #pragma unroll
            for (int kk=0;kk<6;kk++){
                int k0 = kk*16;
                unsigned ua[3][4], ub[4][2];
                #pragma unroll
                for (int mt=0;mt<3;mt++)
                    ldsm4(ua[mt][0],ua[mt][1],ua[mt][2],ua[mt][3],
                          &sFdh[(m0+mt*16+row16)*104 + k0 + half8]);
                #pragma unroll
                for (int np=0;np<2;np++){
                    unsigned t0,t1,t2,t3;
                    ldsm4t(t0,t1,t2,t3, &sWdh[(k0+row16)*136 + n0+np*16 + half8]);
                    ub[2*np][0]=t0; ub[2*np][1]=t1;
                    ub[2*np+1][0]=t2; ub[2*np+1][1]=t3;
                }
                #pragma unroll
                for (int mt=0;mt<3;mt++)
                    #pragma unroll
                    for (int nt=0;nt<4;nt++)
                        mma16(da[mt][nt], ua[mt], ub[nt]);
            }

            #pragma unroll
            for (int mt=0;mt<3;mt++){
                #pragma unroll
                for (int nt=0;nt<4;nt++){
                    int c = n0 + nt*8 + tg*2;
                    #pragma unroll
                    for (int h=0; h<2; h++){
                        int r = m0 + mt*16 + gq + h*8;
                        float v0 = silu_f(da[mt][nt][2*h+0]);
                        float v1 = silu_f(da[mt][nt][2*h+1]);
                        *(unsigned*)&sUh[r*136 + c] = pack_bf2(v0, v1);
                    }
                }
            }
            __syncthreads();   // sync(2): epilogue-A (U) -> GEMM-B; also fences
                               // all GEMM-A reads before next-iter build writes

            float de[3][4][4];
            #pragma unroll
            for (int mt=0;mt<3;mt++)
                #pragma unroll
                for (int nt=0;nt<4;nt++)
                    #pragma unroll
                    for (int q=0;q<4;q++) de[mt][nt][q] = 0.f;
            #pragma unroll
            for (int kk=0;kk<8;kk++){
                int k0 = kk*16;
                unsigned ua[3][4], ub[4][2];
                #pragma unroll
                for (int mt=0;mt<3;mt++)
                    ldsm4(ua[mt][0],ua[mt][1],ua[mt][2],ua[mt][3],
                          &sUh[(m0+mt*16+row16)*136 + k0 + half8]);
                #pragma unroll
                for (int np=0;np<2;np++){
                    unsigned t0,t1,t2,t3;
                    ldsm4t(t0,t1,t2,t3, &sW2h[(k0+row16)*136 + n0+np*16 + half8]);
                    ub[2*np][0]=t0; ub[2*np][1]=t1;
                    ub[2*np+1][0]=t2; ub[2*np+1][1]=t3;
                }
                #pragma unroll
                for (int mt=0;mt<3;mt++)
                    #pragma unroll
                    for (int nt=0;nt<4;nt++)
                        mma16(de[mt][nt], ua[mt], ub[nt]);
            }
            int iA = i0 + wy*2, iB = iA + 1;
            #pragma unroll
            for (int nt=0;nt<4;nt++){
                #pragma unroll
                for (int qq=0;qq<2;qq++){
                    int c = n0 + nt*8 + tg*2 + qq;
                    float b = rb2[nt*2+qq];
                    float s0 = silu_f(de[0][nt][qq]+b) + silu_f(de[0][nt][2+qq]+b)
                             + silu_f(de[1][nt][qq]+b);
                    float s1 = silu_f(de[1][nt][2+qq]+b) + silu_f(de[2][nt][qq]+b)
                             + silu_f(de[2][nt][2+qq]+b);
                    #pragma unroll
                    for (int off=4;off<32;off<<=1){
                        s0 += __shfl_xor_sync(0xffffffffu, s0, off);
                        s1 += __shfl_xor_sync(0xffffffffu, s1, off);
                    }
                    if (gq == 0){
                        d_agg[(gr*24 + iA)*Hd + c] = s0 * (1.0f/24.0f);
                        d_agg[(gr*24 + iB)*Hd + c] = s1 * (1.0f/24.0f);
                    }
                }
            }
            // no end-of-iter sync: next build's writes (sFdh 0-59, sWdh 60-63)
            // conflict only with GEMM-A reads, which sync(2) already fenced;
            // GEMM-B reads (sUh, sW2h) are disjoint from build writes.
        }
    }
}

// ---------------- fused node MLP + next proj (tf32, 2 graphs/CTA) -------------
__global__ void __launch_bounds__(256,2) node_fused(
    const float* __restrict__ nb1, const float* __restrict__ nb2,
    int l, int do_proj)
{
    extern __shared__ __align__(16) unsigned smu[];
    unsigned* sX  = smu;               // [48][260]
    unsigned* sWb = sX + 48*260;       // chunk buffer (8704 u32)
    unsigned* sY  = sWb + 8704;        // [48][132]
    float* sB = (float*)(sY + 48*132); // b1[128] | b2[128]
    unsigned* sH = sY;                 // proj-phase alias

    int r0g = blockIdx.x*48;
    int tx = threadIdx.x;
    int warp = tx>>5, lane = tx&31;
    int gq = lane>>2, tg = lane&3;

    for (int idx=tx; idx<48*64; idx+=256){
        int r = idx>>6; int q = idx&63;
        float4 v = (q<32) ? *(const float4*)&d_h[(r0g+r)*Hd + q*4]
                          : *(const float4*)&d_agg[(r0g+r)*Hd + (q-32)*4];
        uint4 o;
        o.x = tf32_rna(v.x); o.y = tf32_rna(v.y);
        o.z = tf32_rna(v.z); o.w = tf32_rna(v.w);
        *(uint4*)&sX[r*260 + q*4] = o;
    }
    if (tx < 128){ sB[tx] = nb1[l*Hd+tx]; sB[128+tx] = nb2[l*Hd+tx]; }

    float a1[3][2][4];
    #pragma unroll
    for (int mt=0;mt<3;mt++)
        #pragma unroll
        for (int nt=0;nt<2;nt++)
            #pragma unroll
            for (int q=0;q<4;q++) a1[mt][nt][q] = 0.f;

    for (int kc=0; kc<4; kc++){
        {
            const uint4* src = (const uint4*)&d_W1t[(l*256 + kc*64)*136];
            uint4* dst = (uint4*)sWb;
            for (int i=tx; i<2176; i+=256) dst[i] = src[i];
        }
        __syncthreads();
        #pragma unroll
        for (int kk=0;kk<8;kk++){
            int ka = kc*64 + kk*8;
            int kb = kk*8;
            unsigned ua[3][4], ub[2][2];
            #pragma unroll
            for (int mt=0;mt<3;mt++){
                int r = mt*16 + gq;
                ua[mt][0] = sX[r*260 + ka+tg];
                ua[mt][1] = sX[(r+8)*260 + ka+tg];
                ua[mt][2] = sX[r*260 + ka+tg+4];
                ua[mt][3] = sX[(r+8)*260 + ka+tg+4];
            }
            #pragma unroll
            for (int nt=0;nt<2;nt++){
                int c = warp*16 + nt*8 + gq;
                ub[nt][0] = sWb[(kb+tg)*136 + c];
                ub[nt][1] = sWb[(kb+tg+4)*136 + c];
            }
            #pragma unroll
            for (int mt=0;mt<3;mt++)
                #pragma unroll
                for (int nt=0;nt<2;nt++)
                    mma8(a1[mt][nt], ua[mt], ub[nt]);
        }
        __syncthreads();
    }

    #pragma unroll
    for (int mt=0;mt<3;mt++){
        #pragma unroll
        for (int nt=0;nt<2;nt++){
            int c = warp*16 + nt*8 + tg*2;
            #pragma unroll
            for (int h=0;h<2;h++){
                int r = mt*16 + gq + h*8;
                sY[r*132 + c]   = tf32_rna(silu_f(a1[mt][nt][2*h+0] + sB[c]));
                sY[r*132 + c+1] = tf32_rna(silu_f(a1[mt][nt][2*h+1] + sB[c+1]));
            }
        }
    }

    float a2[3][2][4];
    #pragma unroll
    for (int mt=0;mt<3;mt++)
        #pragma unroll
        for (int nt=0;nt<2;nt++)
            #pragma unroll
            for (int q=0;q<4;q++) a2[mt][nt][q] = 0.f;

    for (int kc=0; kc<2; kc++){
        __syncthreads();
        {
            const uint4* src = (const uint4*)&d_W2t[(l*128 + kc*64)*136];
            uint4* dst = (uint4*)sWb;
            for (int i=tx; i<2176; i+=256) dst[i] = src[i];
        }
        __syncthreads();
        #pragma unroll
        for (int kk=0;kk<8;kk++){
            int ka = kc*64 + kk*8;
            int kb = kk*8;
            unsigned ua[3][4], ub[2][2];
            #pragma unroll
            for (int mt=0;mt<3;mt++){
                int r = mt*16 + gq;
                ua[mt][0] = sY[r*132 + ka+tg];
                ua[mt][1] = sY[(r+8)*132 + ka+tg];
                ua[mt][2] = sY[r*132 + ka+tg+4];
                ua[mt][3] = sY[(r+8)*132 + ka+tg+4];
            }
            #pragma unroll
            for (int nt=0;nt<2;nt++){
                int c = warp*16 + nt*8 + gq;
                ub[nt][0] = sWb[(kb+tg)*136 + c];
                ub[nt][1] = sWb[(kb+tg+4)*136 + c];
            }
            #pragma unroll
            for (int mt=0;mt<3;mt++)
                #pragma unroll
                for (int nt=0;nt<2;nt++)
                    mma8(a2[mt][nt], ua[mt], ub[nt]);
        }
    }
    __syncthreads();

    float nh[3][2][4];
    #pragma unroll
    for (int mt=0;mt<3;mt++){
        #pragma unroll
        for (int nt=0;nt<2;nt++){
            int c = warp*16 + nt*8 + tg*2;
            #pragma unroll
            for (int h=0;h<2;h++){
                int r = mt*16 + gq + h*8;
                float o0 = silu_f(a2[mt][nt][2*h+0] + sB[128+c]);
                float o1 = silu_f(a2[mt][nt][2*h+1] + sB[128+c+1]);
                float2* p = (float2*)&d_h[(r0g+r)*Hd + c];
                float2 old = *p;
                old.x += o0; old.y += o1;
                *p = old;
                nh[mt][nt][2*h+0] = old.x;
                nh[mt][nt][2*h+1] = old.y;
            }
        }
    }
    if (!do_proj) return;

    #pragma unroll
    for (int mt=0;mt<3;mt++){
        #pragma unroll
        for (int nt=0;nt<2;nt++){
            int c = warp*16 + nt*8 + tg*2;
            #pragma unroll
            for (int h=0;h<2;h++){
                int r = mt*16 + gq + h*8;
                sH[r*132 + c]   = tf32_rna(nh[mt][nt][2*h+0]);
                sH[r*132 + c+1] = tf32_rna(nh[mt][nt][2*h+1]);
            }
        }
    }
    int lp = l+1;
    float accp[3][4][4];
    #pragma unroll
    for (int mt=0;mt<3;mt++)
        #pragma unroll
        for (int nt=0;nt<4;nt++)
            #pragma unroll
            for (int q=0;q<4;q++) accp[mt][nt][q] = 0.f;

    for (int kc=0; kc<4; kc++){
        __syncthreads();
        {
            const uint4* src = (const uint4*)&d_Wabt[(lp*128 + kc*32)*264];
            uint4* dst = (uint4*)sWb;
            for (int i=tx; i<2112; i+=256) dst[i] = src[i];
        }
        __syncthreads();
        #pragma unroll
        for (int kk=0;kk<4;kk++){
            int ka = kc*32 + kk*8;
            int kb = kk*8;
            unsigned ua[3][4], ub[4][2];
            #pragma unroll
            for (int mt=0;mt<3;mt++){
                int r = mt*16 + gq;
                ua[mt][0] = sH[r*132 + ka+tg];
                ua[mt][1] = sH[(r+8)*132 + ka+tg];
                ua[mt][2] = sH[r*132 + ka+tg+4];
                ua[mt][3] = sH[(r+8)*132 + ka+tg+4];
            }
            #pragma unroll
            for (int nt=0;nt<4;nt++){
                int c = warp*32 + nt*8 + gq;
                ub[nt][0] = sWb[(kb+tg)*264 + c];
                ub[nt][1] = sWb[(kb+tg+4)*264 + c];
            }
            #pragma unroll
            for (int mt=0;mt<3;mt++)
                #pragma unroll
                for (int nt=0;nt<4;nt++)
                    mma8(accp[mt][nt], ua[mt], ub[nt]);
        }
    }
    #pragma unroll
    for (int mt=0;mt<3;mt++){
        #pragma unroll
        for (int nt=0;nt<4;nt++){
            int c = warp*32 + nt*8 + tg*2;
            #pragma unroll
            for (int h=0;h<2;h++){
                int r = mt*16 + gq + h*8;
                float2 v = make_float2(accp[mt][nt][2*h+0], accp[mt][nt][2*h+1]);
                if (c < 128) *(float2*)&d_P[(r0g+r)*Hd + c] = v;
                else         *(float2*)&d_Q[(r0g+r)*Hd + (c-128)] = v;
            }
        }
    }
}

// ---------------- final heads -------------------------------------------------
__global__ void __launch_bounds__(128) final_kernel(
    const float* __restrict__ lat, const float* __restrict__ cw,
    const float* __restrict__ lw, float* __restrict__ out)
{
    __shared__ float sh[24*Hd];
    __shared__ float sgf[Hd];
    __shared__ float smid[9];
    __shared__ float scw[Hd*3];
    int g = blockIdx.x; int tx = threadIdx.x;
    for (int idx=tx; idx<24*Hd; idx+=128) sh[idx] = d_h[g*24*Hd + idx];
    for (int idx=tx; idx<Hd*3; idx+=128) scw[idx] = cw[idx];
    __syncthreads();
    {
        float acc = 0.f;
        #pragma unroll
        for (int a=0;a<24;a++) acc += sh[a*Hd + tx];
        sgf[tx] = acc * (1.0f/24.0f);
    }
    if (tx < 72){
        int n = tx/3; int dd = tx - n*3;
        float s = 0.f;
        #pragma unroll 4
        for (int k=0;k<Hd;k++) s += sh[n*Hd+k]*scw[k*3+dd];
        out[Gn*9 + (g*24+n)*3 + dd] = s;
    }
    __syncthreads();
    if (tx < 9){
        float s = 0.f;
        #pragma unroll 4
        for (int k=0;k<Hd;k++) s += sgf[k]*lw[k*9+tx];
        smid[tx] = s;
    }
    __syncthreads();
    if (tx < 9){
        int r = tx/3; int sc = tx - r*3;
        const float* Lg = lat + g*9;
        out[g*9+tx] = smid[r*3+0]*Lg[0+sc] + smid[r*3+1]*Lg[3+sc]
                    + smid[r*3+2]*Lg[6+sc];
    }
}

// ---------------- launch ------------------------------------------------------
extern "C" void kernel_launch(void* const* d_in, const int* in_sizes, int n_in,
                              void* d_out, int out_size)
{
    const float* t          = (const float*)d_in[0];
    const int*   atom_types = (const int*)  d_in[1];
    const float* frac       = (const float*)d_in[2];
    const float* lattices   = (const float*)d_in[3];
    const float* xrd        = (const float*)d_in[6];
    const float* emb        = (const float*)d_in[7];
    const float* latent_w   = (const float*)d_in[8];
    const float* latent_b   = (const float*)d_in[9];
    const float* edge_w1    = (const float*)d_in[10];
    const float* edge_b1    = (const float*)d_in[11];
    const float* edge_w2    = (const float*)d_in[12];
    const float* edge_b2    = (const float*)d_in[13];
    const float* node_w1    = (const float*)d_in[14];
    const float* node_b1    = (const float*)d_in[15];
    const float* node_w2    = (const float*)d_in[16];
    const float* node_b2    = (const float*)d_in[17];
    const float* coord_w    = (const float*)d_in[18];
    const float* lattice_w  = (const float*)d_in[19];
    float* out = (float*)d_out;

    cudaFuncSetAttribute(edge_kernel,
        cudaFuncAttributeMaxDynamicSharedMemorySize, EDGE_SMEM_BYTES);
    cudaFuncSetAttribute(latent_kernel,
        cudaFuncAttributeMaxDynamicSharedMemorySize, LAT_SMEM_BYTES);
    cudaFuncSetAttribute(node_fused,
        cudaFuncAttributeMaxDynamicSharedMemorySize, NF_SMEM_BYTES);

    trig_kernel<<<(NN*30 + 255)/256, 256>>>(frac);
    latips_kernel<<<(Gn*9 + 255)/256, 256>>>(lattices);
    wconv_kernel<<<(NLAYER*256*136 + 255)/256, 256>>>(edge_w1, edge_w2,
                                                      node_w1, node_w2, latent_w);
    latent_kernel<<<NN/48, 256, LAT_SMEM_BYTES>>>(t, atom_types, xrd, emb, latent_b);

    for (int l=0; l<NLAYER; ++l){
        edge_kernel<<<Gn/2, 256, EDGE_SMEM_BYTES>>>(edge_w1, edge_b1, edge_b2, l);
        node_fused<<<Gn/2, 256, NF_SMEM_BYTES>>>(node_b1, node_b2, l, l < NLAYER-1);
    }

    final_kernel<<<Gn, 128>>>(lattices, coord_w, lattice_w, out);
}

// round 17
// speedup vs baseline: 1.0676x; 1.0159x over previous
#include <cuda_runtime.h>
#include <cuda_bf16.h>

#define Gn 512
#define An 24
#define Hd 128
#define NN (Gn*An)
#define NLAYER 4
#define EINW 325

// edge halves: W2 17408 | Wd(aug) 13056 | U 13056 | Fd 9984 ; floats S,C,Lat
#define EDGE_SMEM_BYTES ((17408+13056+13056+9984)*2 + (720+720+128)*4)
// latent: u32 sXc[48][68] | sWc[64][136] | sH[48][132] | sAt[48]
#define LAT_SMEM_BYTES ((48*68 + 64*136 + 48*132 + 48)*4)
// node_fused: sX [48][260] | chunk 8704 u32 | sY [48][132] | bias
#define NF_SMEM_BYTES ((48*260 + 8704 + 48*132)*4 + 1024)

// ---------------- scratch -----------------------------------------------------
__device__ float d_h[NN*Hd];
__device__ float d_P[NN*Hd];
__device__ float d_Q[NN*Hd];
__device__ float d_agg[NN*Hd];
__device__ float d_ts[NN*30];
__device__ float d_tc[NN*30];
__device__ float d_latips[Gn*9];
__device__ __align__(16) __nv_bfloat16 d_W2bf[NLAYER*128*136];
__device__ __align__(16) __nv_bfloat16 d_Wdbf[NLAYER*96*136];
__device__ __align__(16) unsigned d_W1t[NLAYER*256*136];   // tf32, padded
__device__ __align__(16) unsigned d_W2t[NLAYER*128*136];   // tf32, padded
__device__ __align__(16) unsigned d_Wabt[NLAYER*128*264];  // tf32 Wa|Wb, padded
__device__ __align__(16) unsigned d_Lwt[384*136];          // tf32 latent_w, padded

__device__ __forceinline__ float silu_f(float x){
    return __fdividef(x, 1.0f + __expf(-x));
}

__device__ __forceinline__ unsigned pack_bf2(float lo, float hi){
    unsigned r;
    asm("cvt.rn.bf16x2.f32 %0, %1, %2;" : "=r"(r) : "f"(hi), "f"(lo));
    return r;
}

__device__ __forceinline__ unsigned tf32_rna(float x){
    unsigned u;
    asm("cvt.rna.tf32.f32 %0, %1;" : "=r"(u) : "f"(x));
    return u;
}

__device__ __forceinline__ void ldsm4(unsigned& r0, unsigned& r1, unsigned& r2,
                                      unsigned& r3, const void* p){
    unsigned a = (unsigned)__cvta_generic_to_shared(p);
    asm volatile("ldmatrix.sync.aligned.m8n8.x4.shared.b16 {%0,%1,%2,%3}, [%4];"
        : "=r"(r0), "=r"(r1), "=r"(r2), "=r"(r3) : "r"(a));
}

__device__ __forceinline__ void ldsm4t(unsigned& r0, unsigned& r1, unsigned& r2,
                                       unsigned& r3, const void* p){
    unsigned a = (unsigned)__cvta_generic_to_shared(p);
    asm volatile("ldmatrix.sync.aligned.m8n8.x4.trans.shared.b16 {%0,%1,%2,%3}, [%4];"
        : "=r"(r0), "=r"(r1), "=r"(r2), "=r"(r3) : "r"(a));
}

__device__ __forceinline__ void mma16(float* d, const unsigned* a, const unsigned* b){
    asm volatile(
        "mma.sync.aligned.m16n8k16.row.col.f32.bf16.bf16.f32 "
        "{%0,%1,%2,%3}, {%4,%5,%6,%7}, {%8,%9}, {%0,%1,%2,%3};\n"
        : "+f"(d[0]), "+f"(d[1]), "+f"(d[2]), "+f"(d[3])
        : "r"(a[0]), "r"(a[1]), "r"(a[2]), "r"(a[3]), "r"(b[0]), "r"(b[1]));
}

__device__ __forceinline__ void mma8(float* d, const unsigned* a, const unsigned* b){
    asm volatile(
        "mma.sync.aligned.m16n8k8.row.col.f32.tf32.tf32.f32 "
        "{%0,%1,%2,%3}, {%4,%5,%6,%7}, {%8,%9}, {%0,%1,%2,%3};\n"
        : "+f"(d[0]), "+f"(d[1]), "+f"(d[2]), "+f"(d[3])
        : "r"(a[0]), "r"(a[1]), "r"(a[2]), "r"(a[3]), "r"(b[0]), "r"(b[1]));
}

// ---------------- weight pre-conversion (bf16 + tf32, padded) ------------------
__global__ void wconv_kernel(const float* __restrict__ ew1,
                             const float* __restrict__ ew2,
                             const float* __restrict__ nw1,
                             const float* __restrict__ nw2,
                             const float* __restrict__ lw){
    int idx = blockIdx.x*256 + threadIdx.x;
    if (idx < NLAYER*128*136){
        int l = idx/(128*136); int r = idx - l*128*136;
        int k = r/136, c = r - k*136;
        float v = (c<128) ? ew2[(l*128 + k)*Hd + c] : 0.f;
        d_W2bf[idx] = __float2bfloat16_rn(v);
        d_W2t[idx]  = tf32_rna((c<128) ? nw2[(l*128 + k)*Hd + c] : 0.f);
    }
    if (idx < NLAYER*96*136){
        int l = idx/(96*136); int r = idx - l*96*136;
        int k = r/136, c = r - k*136;
        float v = (k<60 && c<128) ? ew1[(l*EINW + 265 + k)*Hd + c] : 0.f;
        d_Wdbf[idx] = __float2bfloat16_rn(v);
    }
    if (idx < NLAYER*256*136){
        int l = idx/(256*136); int r = idx - l*256*136;
        int k = r/136, c = r - k*136;
        d_W1t[idx] = tf32_rna((c<128) ? nw1[(l*256 + k)*Hd + c] : 0.f);
    }
    if (idx < NLAYER*128*264){
        int l = idx/(128*264); int r = idx - l*128*264;
        int k = r/264, n = r - k*264;
        float v = 0.f;
        if (n < 128)      v = ew1[(l*EINW + k)*Hd + n];
        else if (n < 256) v = ew1[(l*EINW + 128 + k)*Hd + (n-128)];
        d_Wabt[idx] = tf32_rna(v);
    }
    if (idx < 384*136){
        int k = idx/136, c = idx - k*136;
        d_Lwt[idx] = tf32_rna((c<128) ? lw[k*Hd + c] : 0.f);
    }
}

// ---------------- per-node trig tables ----------------------------------------
__global__ void trig_kernel(const float* __restrict__ frac){
    int idx = blockIdx.x*blockDim.x + threadIdx.x;
    if (idx >= NN*30) return;
    int n = idx/30; int r = idx - n*30; int dd = r/10; int f = r - dd*10;
    float x = frac[n*3+dd];
    float th = 6.283185307179586f * (float)f * x;
    d_ts[idx] = sinf(th);
    d_tc[idx] = cosf(th);
}

// ---------------- latent (tf32 MMA) + fused layer-0 projection ----------------
__global__ void __launch_bounds__(256,2) latent_kernel(
    const float* __restrict__ t, const int* __restrict__ atom_types,
    const float* __restrict__ xrd, const float* __restrict__ emb,
    const float* __restrict__ lb)
{
    extern __shared__ __align__(16) unsigned lsm[];
    unsigned* sXc = lsm;                // [48][68]
    unsigned* sWc = lsm + 48*68;        // [64][136]
    unsigned* sH  = lsm + 48*68 + 64*136;  // [48][132]
    int*      sAt = (int*)(sH + 48*132);   // [48]
    unsigned* sWb = lsm;                // proj-phase alias

    int n0 = blockIdx.x*48;
    int gbase = n0/24;
    int tx = threadIdx.x;
    int warp = tx>>5, lane = tx&31;
    int gq = lane>>2, tg = lane&3;

    if (tx < 48) sAt[tx] = atom_types[n0+tx] - 1;
    __syncthreads();

    float acc[3][2][4];
    #pragma unroll
    for (int mt=0;mt<3;mt++)
        #pragma unroll
        for (int nt=0;nt<2;nt++)
            #pragma unroll
            for (int q=0;q<4;q++) acc[mt][nt][q] = 0.f;

    for (int kc=0; kc<6; kc++){
        {
            const uint4* src = (const uint4*)&d_Lwt[(kc*64)*136];
            uint4* dst = (uint4*)sWc;
            for (int i=tx; i<2176; i+=256) dst[i] = src[i];
        }
        for (int idx=tx; idx<48*16; idx+=256){
            int r = idx>>4; int q4 = idx&15; int kk = q4*4;
            int k = kc*64 + kk;
            int g = gbase + (r>=24 ? 1 : 0);
            float4 v;
            if (k < 128)      v = *(const float4*)&emb[sAt[r]*Hd + k];
            else if (k < 256) v = *(const float4*)&t[g*Hd + (k-128)];
            else              v = *(const float4*)&xrd[g*Hd + (k-256)];
            uint4 o;
            o.x = tf32_rna(v.x); o.y = tf32_rna(v.y);
            o.z = tf32_rna(v.z); o.w = tf32_rna(v.w);
            *(uint4*)&sXc[r*68 + kk] = o;
        }
        __syncthreads();
        #pragma unroll
        for (int kk=0;kk<8;kk++){
            int k0 = kk*8;
            unsigned ua[3][4], ub[2][2];
            #pragma unroll
            for (int mt=0;mt<3;mt++){
                int r = mt*16 + gq;
                ua[mt][0] = sXc[r*68 + k0+tg];
                ua[mt][1] = sXc[(r+8)*68 + k0+tg];
                ua[mt][2] = sXc[r*68 + k0+tg+4];
                ua[mt][3] = sXc[(r+8)*68 + k0+tg+4];
            }
            #pragma unroll
            for (int nt=0;nt<2;nt++){
                int c = warp*16 + nt*8 + gq;
                ub[nt][0] = sWc[(k0+tg)*136 + c];
                ub[nt][1] = sWc[(k0+tg+4)*136 + c];
            }
            #pragma unroll
            for (int mt=0;mt<3;mt++)
                #pragma unroll
                for (int nt=0;nt<2;nt++)
                    mma8(acc[mt][nt], ua[mt], ub[nt]);
        }
        __syncthreads();
    }

    #pragma unroll
    for (int mt=0;mt<3;mt++){
        #pragma unroll
        for (int nt=0;nt<2;nt++){
            int c = warp*16 + nt*8 + tg*2;
            float b0 = lb[c], b1 = lb[c+1];
            #pragma unroll
            for (int h=0;h<2;h++){
                int r = mt*16 + gq + h*8;
                float h0 = acc[mt][nt][2*h+0] + b0;
                float h1 = acc[mt][nt][2*h+1] + b1;
                *(float2*)&d_h[(n0+r)*Hd + c] = make_float2(h0, h1);
                sH[r*132 + c]   = tf32_rna(h0);
                sH[r*132 + c+1] = tf32_rna(h1);
            }
        }
    }

    float accp[3][4][4];
    #pragma unroll
    for (int mt=0;mt<3;mt++)
        #pragma unroll
        for (int nt=0;nt<4;nt++)
            #pragma unroll
            for (int q=0;q<4;q++) accp[mt][nt][q] = 0.f;

    for (int kc=0; kc<4; kc++){
        if (kc > 0) __syncthreads();   // kc==0: sXc/sWc reads fenced by phase-1
                                       // trailing sync; sH fenced by stage-sync
        {
            const uint4* src = (const uint4*)&d_Wabt[(kc*32)*264];
            uint4* dst = (uint4*)sWb;
            for (int i=tx; i<2112; i+=256) dst[i] = src[i];
        }
        __syncthreads();
        #pragma unroll
        for (int kk=0;kk<4;kk++){
            int ka = kc*32 + kk*8;
            int kb = kk*8;
            unsigned ua[3][4], ub[4][2];
            #pragma unroll
            for (int mt=0;mt<3;mt++){
                int r = mt*16 + gq;
                ua[mt][0] = sH[r*132 + ka+tg];
                ua[mt][1] = sH[(r+8)*132 + ka+tg];
                ua[mt][2] = sH[r*132 + ka+tg+4];
                ua[mt][3] = sH[(r+8)*132 + ka+tg+4];
            }
            #pragma unroll
            for (int nt=0;nt<4;nt++){
                int c = warp*32 + nt*8 + gq;
                ub[nt][0] = sWb[(kb+tg)*264 + c];
                ub[nt][1] = sWb[(kb+tg+4)*264 + c];
            }
            #pragma unroll
            for (int mt=0;mt<3;mt++)
                #pragma unroll
                for (int nt=0;nt<4;nt++)
                    mma8(accp[mt][nt], ua[mt], ub[nt]);
        }
    }
    #pragma unroll
    for (int mt=0;mt<3;mt++){
        #pragma unroll
        for (int nt=0;nt<4;nt++){
            int c = warp*32 + nt*8 + tg*2;
            #pragma unroll
            for (int h=0;h<2;h++){
                int r = mt*16 + gq + h*8;
                float2 v = make_float2(accp[mt][nt][2*h+0], accp[mt][nt][2*h+1]);
                if (c < 128) *(float2*)&d_P[(n0+r)*Hd + c] = v;
                else         *(float2*)&d_Q[(n0+r)*Hd + (c-128)] = v;
            }
        }
    }
}

// ---------------- lattice inner products --------------------------------------
__global__ void latips_kernel(const float* __restrict__ lat){
    int idx = blockIdx.x*blockDim.x + threadIdx.x;
    if (idx >= Gn*9) return;
    int g = idx/9; int rs = idx - g*9; int r = rs/3; int s = rs - r*3;
    const float* Lg = lat + g*9;
    d_latips[idx] = Lg[r*3]*Lg[s*3] + Lg[r*3+1]*Lg[s*3+1] + Lg[r*3+2]*Lg[s*3+2];
}

// ---------------- hot kernel: persistent bf16 edge MLP ------------------------
__global__ void __launch_bounds__(256,2) edge_kernel(
    const float* __restrict__ ew1, const float* __restrict__ eb1,
    const float* __restrict__ eb2, int l)
{
    extern __shared__ __align__(16) unsigned char smraw[];
    __nv_bfloat16* sW2h = (__nv_bfloat16*)smraw;     // [128][136]
    __nv_bfloat16* sWdh = sW2h + 17408;              // [96][136]
    __nv_bfloat16* sUh  = sWdh + 13056;              // [96][136]
    __nv_bfloat16* sFdh = sUh + 13056;               // [96][104]
    float* sS   = (float*)(sFdh + 9984);             // [24][30]
    float* sC   = sS  + 720;
    float* sLat = sC  + 720;                         // [128]

    int tx = threadIdx.x;
    int warp = tx>>5, lane = tx&31;
    int gq = lane>>2, tg = lane&3;
    int wx = warp&3, wy = warp>>2;
    int n0 = wx*32, m0 = wy*48;
    int row16 = lane & 15;
    int half8 = (lane & 16) ? 8 : 0;

    {
        const uint4* s2 = (const uint4*)&d_W2bf[l*128*136];
        uint4* t2 = (uint4*)sW2h;
        for (int i=tx; i<128*136/8; i+=256) t2[i] = s2[i];
        const uint4* sd = (const uint4*)&d_Wdbf[l*96*136];
        uint4* td = (uint4*)sWdh;
        for (int i=tx; i<64*136/8; i+=256) td[i] = sd[i];
        for (int i=tx; i<8*136/8;  i+=256) td[1496+i] = sd[1496+i];
    }
    // one-hot Fd block (cols 60-95): invariant across tiles AND graphs
    for (int idx=tx; idx<96*36; idx+=256){
        int e = idx/36; int k = 60 + (idx - e*36);
        int s = e/24; int j = e - s*24;
        float v = (k == 60+s || k == 64+j) ? 1.f : 0.f;
        sFdh[e*104 + k] = __float2bfloat16_rn(v);
    }
    float rb2[8];
    #pragma unroll
    for (int nt=0;nt<4;nt++)
        #pragma unroll
        for (int qq=0;qq<2;qq++)
            rb2[nt*2+qq] = eb2[l*Hd + n0 + nt*8 + tg*2 + qq];

    for (int gr = blockIdx.x; gr < Gn; gr += gridDim.x){
        for (int idx=tx; idx<24*32; idx+=256){
            int j = idx>>5, qq = idx&31;
            float4 v = *(const float4*)&d_Q[(gr*24+j)*Hd + qq*4];
            unsigned lo = pack_bf2(v.x, v.y);
            unsigned hi = pack_bf2(v.z, v.w);
            *(uint2*)&sWdh[(64+j)*136 + qq*4] = make_uint2(lo, hi);
        }
        for (int idx=tx; idx<720; idx+=256){
            sS[idx] = d_ts[gr*720 + idx];
            sC[idx] = d_tc[gr*720 + idx];
        }
        if (tx < 128){
            float acc = eb1[l*Hd + tx];
            const float* wc = ew1 + (l*EINW + 256)*Hd;
            #pragma unroll
            for (int k=0;k<9;k++) acc += d_latips[gr*9+k] * wc[k*Hd + tx];
            sLat[tx] = acc;
        }
        __syncthreads();

        for (int it=0; it<6; ++it){
            int i0 = it*4;
            // trig pairs (cols 0-59), vectorized over df pairs:
            // j*30 is even => (j*30+df) even for even df => float2-aligned
            for (int idx=tx; idx<96*15; idx+=256){
                int e = idx/15; int df = (idx - e*15)*2;
                int s = e/24; int j = e - s*24; int i = i0+s;
                float2 sjp = *(const float2*)&sS[j*30+df];
                float2 cjp = *(const float2*)&sC[j*30+df];
                float2 sip = *(const float2*)&sS[i*30+df];
                float2 cip = *(const float2*)&sC[i*30+df];
                float v0 = sjp.x*cip.x - cjp.x*sip.x;
                float v1 = sjp.y*cip.y - cjp.y*sip.y;
                float w0 = cjp.x*cip.x + sjp.x*sip.x;
                float w1 = cjp.y*cip.y + sjp.y*sip.y;
                *(unsigned*)&sFdh[e*104 + df]      = pack_bf2(v0, v1);
                *(unsigned*)&sFdh[e*104 + 30 + df] = pack_bf2(w0, w1);
            }
            for (int idx=tx; idx<4*Hd; idx+=256){
                int s = idx>>7, c = idx&127;
                sWdh[(60+s)*136 + c] =
                    __float2bfloat16_rn(d_P[(gr*24+i0+s)*Hd + c] + sLat[c]);
            }
            __syncthreads();   // sync(1): build -> GEMM-A

            float da[3][4][4];
            #pragma unroll
            for (int mt=0;mt<3;mt++)
                #pragma unroll
                for (int nt=0;nt<4;nt++)
                    #pragma unroll
                    for (int q=0;q<4;q++) da[mt][nt][q] = 0.f;
            #pragma unroll
            for (int kk=0;kk<6;kk++){
                int k0 = kk*16;
                unsigned ua[3][4], ub[4][2];
                #pragma unroll
                for (int mt=0;mt<3;mt++)
                    ldsm4(ua[mt][0],ua[mt][1],ua[mt][2],ua[mt][3],
                          &sFdh[(m0+mt*16+row16)*104 + k0 + half8]);
                #pragma unroll
                for (int np=0;np<2;np++){
                    unsigned t0,t1,t2,t3;
                    ldsm4t(t0,t1,t2,t3, &sWdh[(k0+row16)*136 + n0+np*16 + half8]);
                    ub[2*np][0]=t0; ub[2*np][1]=t1;
                    ub[2*np+1][0]=t2; ub[2*np+1][1]=t3;
                }
                #pragma unroll
                for (int mt=0;mt<3;mt++)
                    #pragma unroll
                    for (int nt=0;nt<4;nt++)
                        mma16(da[mt][nt], ua[mt], ub[nt]);
            }

            #pragma unroll
            for (int mt=0;mt<3;mt++){
                #pragma unroll
                for (int nt=0;nt<4;nt++){
                    int c = n0 + nt*8 + tg*2;
                    #pragma unroll
                    for (int h=0; h<2; h++){
                        int r = m0 + mt*16 + gq + h*8;
                        float v0 = silu_f(da[mt][nt][2*h+0]);
                        float v1 = silu_f(da[mt][nt][2*h+1]);
                        *(unsigned*)&sUh[r*136 + c] = pack_bf2(v0, v1);
                    }
                }
            }
            __syncthreads();   // sync(2): U -> GEMM-B; also fences GEMM-A reads
                               // before next-iter build writes

            float de[3][4][4];
            #pragma unroll
            for (int mt=0;mt<3;mt++)
                #pragma unroll
                for (int nt=0;nt<4;nt++)
                    #pragma unroll
                    for (int q=0;q<4;q++) de[mt][nt][q] = 0.f;
            #pragma unroll
            for (int kk=0;kk<8;kk++){
                int k0 = kk*16;
                unsigned ua[3][4], ub[4][2];
                #pragma unroll
                for (int mt=0;mt<3;mt++)
                    ldsm4(ua[mt][0],ua[mt][1],ua[mt][2],ua[mt][3],
                          &sUh[(m0+mt*16+row16)*136 + k0 + half8]);
                #pragma unroll
                for (int np=0;np<2;np++){
                    unsigned t0,t1,t2,t3;
                    ldsm4t(t0,t1,t2,t3, &sW2h[(k0+row16)*136 + n0+np*16 + half8]);
                    ub[2*np][0]=t0; ub[2*np][1]=t1;
                    ub[2*np+1][0]=t2; ub[2*np+1][1]=t3;
                }
                #pragma unroll
                for (int mt=0;mt<3;mt++)
                    #pragma unroll
                    for (int nt=0;nt<4;nt++)
                        mma16(de[mt][nt], ua[mt], ub[nt]);
            }
            int iA = i0 + wy*2, iB = iA + 1;
            #pragma unroll
            for (int nt=0;nt<4;nt++){
                #pragma unroll
                for (int qq=0;qq<2;qq++){
                    int c = n0 + nt*8 + tg*2 + qq;
                    float b = rb2[nt*2+qq];
                    float s0 = silu_f(de[0][nt][qq]+b) + silu_f(de[0][nt][2+qq]+b)
                             + silu_f(de[1][nt][qq]+b);
                    float s1 = silu_f(de[1][nt][2+qq]+b) + silu_f(de[2][nt][qq]+b)
                             + silu_f(de[2][nt][2+qq]+b);
                    #pragma unroll
                    for (int off=4;off<32;off<<=1){
                        s0 += __shfl_xor_sync(0xffffffffu, s0, off);
                        s1 += __shfl_xor_sync(0xffffffffu, s1, off);
                    }
                    if (gq == 0){
                        d_agg[(gr*24 + iA)*Hd + c] = s0 * (1.0f/24.0f);
                        d_agg[(gr*24 + iB)*Hd + c] = s1 * (1.0f/24.0f);
                    }
                }
            }
            // no end-of-iter sync (proof in R16)
        }
    }
}

// ---------------- fused node MLP + next proj (tf32, 2 graphs/CTA) -------------
__global__ void __launch_bounds__(256,2) node_fused(
    const float* __restrict__ nb1, const float* __restrict__ nb2,
    int l, int do_proj)
{
    extern __shared__ __align__(16) unsigned smu[];
    unsigned* sX  = smu;               // [48][260]
    unsigned* sWb = sX + 48*260;       // chunk buffer (8704 u32)
    unsigned* sY  = sWb + 8704;        // [48][132]
    float* sB = (float*)(sY + 48*132); // b1[128] | b2[128]
    unsigned* sH = sY;                 // proj-phase alias

    int r0g = blockIdx.x*48;
    int tx = threadIdx.x;
    int warp = tx>>5, lane = tx&31;
    int gq = lane>>2, tg = lane&3;

    for (int idx=tx; idx<48*64; idx+=256){
        int r = idx>>6; int q = idx&63;
        float4 v = (q<32) ? *(const float4*)&d_h[(r0g+r)*Hd + q*4]
                          : *(const float4*)&d_agg[(r0g+r)*Hd + (q-32)*4];
        uint4 o;
        o.x = tf32_rna(v.x); o.y = tf32_rna(v.y);
        o.z = tf32_rna(v.z); o.w = tf32_rna(v.w);
        *(uint4*)&sX[r*260 + q*4] = o;
    }
    if (tx < 128){ sB[tx] = nb1[l*Hd+tx]; sB[128+tx] = nb2[l*Hd+tx]; }

    float a1[3][2][4];
    #pragma unroll
    for (int mt=0;mt<3;mt++)
        #pragma unroll
        for (int nt=0;nt<2;nt++)
            #pragma unroll
            for (int q=0;q<4;q++) a1[mt][nt][q] = 0.f;

    for (int kc=0; kc<4; kc++){
        {
            const uint4* src = (const uint4*)&d_W1t[(l*256 + kc*64)*136];
            uint4* dst = (uint4*)sWb;
            for (int i=tx; i<2176; i+=256) dst[i] = src[i];
        }
        __syncthreads();
        #pragma unroll
        for (int kk=0;kk<8;kk++){
            int ka = kc*64 + kk*8;
            int kb = kk*8;
            unsigned ua[3][4], ub[2][2];
            #pragma unroll
            for (int mt=0;mt<3;mt++){
                int r = mt*16 + gq;
                ua[mt][0] = sX[r*260 + ka+tg];
                ua[mt][1] = sX[(r+8)*260 + ka+tg];
                ua[mt][2] = sX[r*260 + ka+tg+4];
                ua[mt][3] = sX[(r+8)*260 + ka+tg+4];
            }
            #pragma unroll
            for (int nt=0;nt<2;nt++){
                int c = warp*16 + nt*8 + gq;
                ub[nt][0] = sWb[(kb+tg)*136 + c];
                ub[nt][1] = sWb[(kb+tg+4)*136 + c];
            }
            #pragma unroll
            for (int mt=0;mt<3;mt++)
                #pragma unroll
                for (int nt=0;nt<2;nt++)
                    mma8(a1[mt][nt], ua[mt], ub[nt]);
        }
        __syncthreads();
    }

    #pragma unroll
    for (int mt=0;mt<3;mt++){
        #pragma unroll
        for (int nt=0;nt<2;nt++){
            int c = warp*16 + nt*8 + tg*2;
            #pragma unroll
            for (int h=0;h<2;h++){
                int r = mt*16 + gq + h*8;
                sY[r*132 + c]   = tf32_rna(silu_f(a1[mt][nt][2*h+0] + sB[c]));
                sY[r*132 + c+1] = tf32_rna(silu_f(a1[mt][nt][2*h+1] + sB[c+1]));
            }
        }
    }

    float a2[3][2][4];
    #pragma unroll
    for (int mt=0;mt<3;mt++)
        #pragma unroll
        for (int nt=0;nt<2;nt++)
            #pragma unroll
            for (int q=0;q<4;q++) a2[mt][nt][q] = 0.f;

    for (int kc=0; kc<2; kc++){
        if (kc > 0) __syncthreads();   // kc==0: sWb reads fenced by GEMM1's
                                       // trailing sync; sY by stage-sync
        {
            const uint4* src = (const uint4*)&d_W2t[(l*128 + kc*64)*136];
            uint4* dst = (uint4*)sWb;
            for (int i=tx; i<2176; i+=256) dst[i] = src[i];
        }
        __syncthreads();
        #pragma unroll
        for (int kk=0;kk<8;kk++){
            int ka = kc*64 + kk*8;
            int kb = kk*8;
            unsigned ua[3][4], ub[2][2];
            #pragma unroll
            for (int mt=0;mt<3;mt++){
                int r = mt*16 + gq;
                ua[mt][0] = sY[r*132 + ka+tg];
                ua[mt][1] = sY[(r+8)*132 + ka+tg];
                ua[mt][2] = sY[r*132 + ka+tg+4];
                ua[mt][3] = sY[(r+8)*132 + ka+tg+4];
            }
            #pragma unroll
            for (int nt=0;nt<2;nt++){
                int c = warp*16 + nt*8 + gq;
                ub[nt][0] = sWb[(kb+tg)*136 + c];
                ub[nt][1] = sWb[(kb+tg+4)*136 + c];
            }
            #pragma unroll
            for (int mt=0;mt<3;mt++)
                #pragma unroll
                for (int nt=0;nt<2;nt++)
                    mma8(a2[mt][nt], ua[mt], ub[nt]);
        }
    }
    __syncthreads();

    float nh[3][2][4];
    #pragma unroll
    for (int mt=0;mt<3;mt++){
        #pragma unroll
        for (int nt=0;nt<2;nt++){
            int c = warp*16 + nt*8 + tg*2;
            #pragma unroll
            for (int h=0;h<2;h++){
                int r = mt*16 + gq + h*8;
                float o0 = silu_f(a2[mt][nt][2*h+0] + sB[128+c]);
                float o1 = silu_f(a2[mt][nt][2*h+1] + sB[128+c+1]);
                float2* p = (float2*)&d_h[(r0g+r)*Hd + c];
                float2 old = *p;
                old.x += o0; old.y += o1;
                *p = old;
                nh[mt][nt][2*h+0] = old.x;
                nh[mt][nt][2*h+1] = old.y;
            }
        }
    }
    if (!do_proj) return;

    #pragma unroll
    for (int mt=0;mt<3;mt++){
        #pragma unroll
        for (int nt=0;nt<2;nt++){
            int c = warp*16 + nt*8 + tg*2;
            #pragma unroll
            for (int h=0;h<2;h++){
                int r = mt*16 + gq + h*8;
                sH[r*132 + c]   = tf32_rna(nh[mt][nt][2*h+0]);
                sH[r*132 + c+1] = tf32_rna(nh[mt][nt][2*h+1]);
            }
        }
    }
    int lp = l+1;
    float accp[3][4][4];
    #pragma unroll
    for (int mt=0;mt<3;mt++)
        #pragma unroll
        for (int nt=0;nt<4;nt++)
            #pragma unroll
            for (int q=0;q<4;q++) accp[mt][nt][q] = 0.f;

    for (int kc=0; kc<4; kc++){
        if (kc > 0) __syncthreads();   // kc==0: sWb reads fenced by post-GEMM2
                                       // sync; sH writes fenced by stage-sync
        {
            const uint4* src = (const uint4*)&d_Wabt[(lp*128 + kc*32)*264];
            uint4* dst = (uint4*)sWb;
            for (int i=tx; i<2112; i+=256) dst[i] = src[i];
        }
        __syncthreads();
        #pragma unroll
        for (int kk=0;kk<4;kk++){
            int ka = kc*32 + kk*8;
            int kb = kk*8;
            unsigned ua[3][4], ub[4][2];
            #pragma unroll
            for (int mt=0;mt<3;mt++){
                int r = mt*16 + gq;
                ua[mt][0] = sH[r*132 + ka+tg];
                ua[mt][1] = sH[(r+8)*132 + ka+tg];
                ua[mt][2] = sH[r*132 + ka+tg+4];
                ua[mt][3] = sH[(r+8)*132 + ka+tg+4];
            }
            #pragma unroll
            for (int nt=0;nt<4;nt++){
                int c = warp*32 + nt*8 + gq;
                ub[nt][0] = sWb[(kb+tg)*264 + c];
                ub[nt][1] = sWb[(kb+tg+4)*264 + c];
            }
            #pragma unroll
            for (int mt=0;mt<3;mt++)
                #pragma unroll
                for (int nt=0;nt<4;nt++)
                    mma8(accp[mt][nt], ua[mt], ub[nt]);
        }
    }
    #pragma unroll
    for (int mt=0;mt<3;mt++){
        #pragma unroll
        for (int nt=0;nt<4;nt++){
            int c = warp*32 + nt*8 + tg*2;
            #pragma unroll
            for (int h=0;h<2;h++){
                int r = mt*16 + gq + h*8;
                float2 v = make_float2(accp[mt][nt][2*h+0], accp[mt][nt][2*h+1]);
                if (c < 128) *(float2*)&d_P[(r0g+r)*Hd + c] = v;
                else         *(float2*)&d_Q[(r0g+r)*Hd + (c-128)] = v;
            }
        }
    }
}

// ---------------- final heads -------------------------------------------------
__global__ void __launch_bounds__(128) final_kernel(
    const float* __restrict__ lat, const float* __restrict__ cw,
    const float* __restrict__ lw, float* __restrict__ out)
{
    __shared__ float sh[24*Hd];
    __shared__ float sgf[Hd];
    __shared__ float smid[9];
    __shared__ float scw[Hd*3];
    int g = blockIdx.x; int tx = threadIdx.x;
    for (int idx=tx; idx<24*Hd; idx+=128) sh[idx] = d_h[g*24*Hd + idx];
    for (int idx=tx; idx<Hd*3; idx+=128) scw[idx] = cw[idx];
    __syncthreads();
    {
        float acc = 0.f;
        #pragma unroll
        for (int a=0;a<24;a++) acc += sh[a*Hd + tx];
        sgf[tx] = acc * (1.0f/24.0f);
    }
    if (tx < 72){
        int n = tx/3; int dd = tx - n*3;
        float s = 0.f;
        #pragma unroll 4
        for (int k=0;k<Hd;k++) s += sh[n*Hd+k]*scw[k*3+dd];
        out[Gn*9 + (g*24+n)*3 + dd] = s;
    }
    __syncthreads();
    if (tx < 9){
        float s = 0.f;
        #pragma unroll 4
        for (int k=0;k<Hd;k++) s += sgf[k]*lw[k*9+tx];
        smid[tx] = s;
    }
    __syncthreads();
    if (tx < 9){
        int r = tx/3; int sc = tx - r*3;
        const float* Lg = lat + g*9;
        out[g*9+tx] = smid[r*3+0]*Lg[0+sc] + smid[r*3+1]*Lg[3+sc]
                    + smid[r*3+2]*Lg[6+sc];
    }
}

// ---------------- launch ------------------------------------------------------
extern "C" void kernel_launch(void* const* d_in, const int* in_sizes, int n_in,
                              void* d_out, int out_size)
{
    const float* t          = (const float*)d_in[0];
    const int*   atom_types = (const int*)  d_in[1];
    const float* frac       = (const float*)d_in[2];
    const float* lattices   = (const float*)d_in[3];
    const float* xrd        = (const float*)d_in[6];
    const float* emb        = (const float*)d_in[7];
    const float* latent_w   = (const float*)d_in[8];
    const float* latent_b   = (const float*)d_in[9];
    const float* edge_w1    = (const float*)d_in[10];
    const float* edge_b1    = (const float*)d_in[11];
    const float* edge_w2    = (const float*)d_in[12];
    const float* edge_b2    = (const float*)d_in[13];
    const float* node_w1    = (const float*)d_in[14];
    const float* node_b1    = (const float*)d_in[15];
    const float* node_w2    = (const float*)d_in[16];
    const float* node_b2    = (const float*)d_in[17];
    const float* coord_w    = (const float*)d_in[18];
    const float* lattice_w  = (const float*)d_in[19];
    float* out = (float*)d_out;

    cudaFuncSetAttribute(edge_kernel,
        cudaFuncAttributeMaxDynamicSharedMemorySize, EDGE_SMEM_BYTES);
    cudaFuncSetAttribute(latent_kernel,
        cudaFuncAttributeMaxDynamicSharedMemorySize, LAT_SMEM_BYTES);
    cudaFuncSetAttribute(node_fused,
        cudaFuncAttributeMaxDynamicSharedMemorySize, NF_SMEM_BYTES);

    trig_kernel<<<(NN*30 + 255)/256, 256>>>(frac);
    latips_kernel<<<(Gn*9 + 255)/256, 256>>>(lattices);
    wconv_kernel<<<(NLAYER*256*136 + 255)/256, 256>>>(edge_w1, edge_w2,
                                                      node_w1, node_w2, latent_w);
    latent_kernel<<<NN/48, 256, LAT_SMEM_BYTES>>>(t, atom_types, xrd, emb, latent_b);

    for (int l=0; l<NLAYER; ++l){
        edge_kernel<<<Gn/2, 256, EDGE_SMEM_BYTES>>>(edge_w1, edge_b1, edge_b2, l);
        node_fused<<<Gn/2, 256, NF_SMEM_BYTES>>>(node_b1, node_b2, l, l < NLAYER-1);
    }

    final_kernel<<<Gn, 128>>>(lattices, coord_w, lattice_w, out);
}